// round 1
// baseline (speedup 1.0000x reference)
#include <cuda_runtime.h>
#include <cstdint>

#define BATCH 8
#define NUM_PM 300
#define NUM_VM 1000
#define PM_COV 8
#define DMODEL 256
#define NHEAD 8
#define DHEAD 32
#define DFF 1024
#define NLAYER 3
#define SEQL (NUM_PM + NUM_VM + 2)   // 1302
#define MROWS (BATCH * SEQL)          // 10416

// ---------------- static scratch (no allocation allowed) ----------------
__device__ float g_x[MROWS * DMODEL];
__device__ float g_h[MROWS * DMODEL];
__device__ float g_q[MROWS * DMODEL];
__device__ float g_k[MROWS * DMODEL];
__device__ float g_v[MROWS * DMODEL];
__device__ float g_o[MROWS * DMODEL];
__device__ float g_ffn[MROWS * DFF];
__device__ int   g_rel[MROWS];

// ---------------- embed + rel ----------------
__global__ void embed_kernel(const float* __restrict__ vm_states,
                             const float* __restrict__ num_step,
                             const float* __restrict__ pm_states,
                             const float* __restrict__ W_pm, const float* __restrict__ b_pm,
                             const float* __restrict__ W_vm, const float* __restrict__ b_vm,
                             const float* __restrict__ critic) {
    int b = blockIdx.y;
    int l = blockIdx.x;
    int d = threadIdx.x;
    float val;
    if (l == 0) {
        val = num_step[b];
    } else if (l <= NUM_PM) {
        const float* pm = pm_states + ((size_t)b * NUM_PM + (l - 1)) * PM_COV;
        float acc = b_pm[d];
        #pragma unroll
        for (int c = 0; c < PM_COV; c++) acc += pm[c] * W_pm[c * DMODEL + d];
        val = acc;
    } else if (l <= NUM_PM + NUM_VM) {
        const float* vm = vm_states + ((size_t)b * NUM_VM + (l - 1 - NUM_PM)) * 7;
        float acc = b_vm[d];
        #pragma unroll
        for (int c = 0; c < 6; c++) acc += vm[c] * W_vm[c * DMODEL + d];
        val = acc;
    } else {
        val = critic[d];
    }
    g_x[((size_t)b * SEQL + l) * DMODEL + d] = val;
    if (d == 0) {
        int r = -100;
        if (l >= 1 && l <= NUM_PM) r = l - 1;
        else if (l > NUM_PM && l < SEQL - 1)
            r = (int)vm_states[((size_t)b * NUM_VM + (l - 1 - NUM_PM)) * 7 + 6];
        g_rel[b * SEQL + l] = r;
    }
}

// ---------------- layernorm (row of 256) ----------------
__global__ void ln_kernel(const float* __restrict__ gamma, const float* __restrict__ beta) {
    int row = blockIdx.x;
    int d = threadIdx.x;
    float v = g_x[(size_t)row * DMODEL + d];
    __shared__ float red[8];
    __shared__ float bc_mean, bc_var;
    float s = v;
    #pragma unroll
    for (int o = 16; o > 0; o >>= 1) s += __shfl_xor_sync(0xffffffffu, s, o);
    if ((d & 31) == 0) red[d >> 5] = s;
    __syncthreads();
    if (d == 0) {
        float t = 0.f;
        #pragma unroll
        for (int i = 0; i < 8; i++) t += red[i];
        bc_mean = t * (1.0f / DMODEL);
    }
    __syncthreads();
    float mean = bc_mean;
    float c = v - mean;
    float cs = c * c;
    #pragma unroll
    for (int o = 16; o > 0; o >>= 1) cs += __shfl_xor_sync(0xffffffffu, cs, o);
    if ((d & 31) == 0) red[d >> 5] = cs;
    __syncthreads();
    if (d == 0) {
        float t = 0.f;
        #pragma unroll
        for (int i = 0; i < 8; i++) t += red[i];
        bc_var = t * (1.0f / DMODEL);
    }
    __syncthreads();
    float r = rsqrtf(bc_var + 1e-5f);
    g_h[(size_t)row * DMODEL + d] = c * r * gamma[d] + beta[d];
}

// ---------------- GELU (tanh approximation, matches jax.nn.gelu default) ----------------
__device__ __forceinline__ float gelu_f(float x) {
    float x3 = x * x * x;
    float t = tanhf(0.7978845608028654f * (x + 0.044715f * x3));
    return 0.5f * x * (1.0f + t);
}

// ---------------- tiled sgemm: C[M,N] = A[M,K] @ W[K,N] + bias (+res) (opt gelu) ----------------
#define BM 64
#define BN 64
#define BKK 16
__global__ void sgemm_kernel(const float* __restrict__ A, const float* __restrict__ W,
                             const float* __restrict__ bias, float* __restrict__ C,
                             const float* __restrict__ res,
                             int M, int N, int K, int act) {
    __shared__ float As[BKK][BM];
    __shared__ float Bs[BKK][BN];
    int tx = threadIdx.x & 15;
    int ty = threadIdx.x >> 4;
    int m0 = blockIdx.y * BM;
    int n0 = blockIdx.x * BN;
    float acc[4][4] = {};
    for (int k0 = 0; k0 < K; k0 += BKK) {
        #pragma unroll
        for (int i = 0; i < 4; i++) {
            int idx = threadIdx.x + i * 256;
            int mm = idx >> 4, kk = idx & 15;
            int gm = m0 + mm;
            As[kk][mm] = (gm < M) ? A[(size_t)gm * K + k0 + kk] : 0.f;
        }
        #pragma unroll
        for (int i = 0; i < 4; i++) {
            int idx = threadIdx.x + i * 256;
            int kk = idx >> 6, nn = idx & 63;
            Bs[kk][nn] = W[(size_t)(k0 + kk) * N + n0 + nn];
        }
        __syncthreads();
        #pragma unroll
        for (int kk = 0; kk < BKK; kk++) {
            float a[4], bb[4];
            #pragma unroll
            for (int i = 0; i < 4; i++) a[i] = As[kk][ty * 4 + i];
            #pragma unroll
            for (int j = 0; j < 4; j++) bb[j] = Bs[kk][tx * 4 + j];
            #pragma unroll
            for (int i = 0; i < 4; i++)
                #pragma unroll
                for (int j = 0; j < 4; j++)
                    acc[i][j] += a[i] * bb[j];
        }
        __syncthreads();
    }
    #pragma unroll
    for (int i = 0; i < 4; i++) {
        int gm = m0 + ty * 4 + i;
        if (gm >= M) continue;
        #pragma unroll
        for (int j = 0; j < 4; j++) {
            int gn = n0 + tx * 4 + j;
            float v = acc[i][j] + bias[gn];
            if (res) v += res[(size_t)gm * N + gn];
            if (act) v = gelu_f(v);
            C[(size_t)gm * N + gn] = v;
        }
    }
}

// ---------------- sparse masked attention (online softmax, skip masked keys) ----------------
__global__ void attn_kernel() {
    int b = blockIdx.z;
    int h = blockIdx.y;
    int l = blockIdx.x * 256 + threadIdx.x;
    bool valid = (l < SEQL);

    float q[DHEAD];
    float o[DHEAD];
    #pragma unroll
    for (int d = 0; d < DHEAD; d++) o[d] = 0.f;
    float m = -1e30f, ssum = 0.f;
    int myrel = -999;
    if (valid) {
        const float* qp = g_q + ((size_t)b * SEQL + l) * DMODEL + h * DHEAD;
        #pragma unroll
        for (int d = 0; d < DHEAD; d++) q[d] = qp[d] * 0.17677669529663687f; // 1/sqrt(32)
        myrel = (l == 0) ? -10 : ((l == SEQL - 1) ? -11 : g_rel[b * SEQL + l]);
    }

    __shared__ float ks[64 * DHEAD];
    __shared__ float vs[64 * DHEAD];
    __shared__ int rels[64];

    for (int kc = 0; kc < SEQL; kc += 64) {
        __syncthreads();
        for (int i = threadIdx.x; i < 64 * DHEAD; i += 256) {
            int j = i >> 5, d = i & 31;
            int kk = kc + j;
            float kv = 0.f, vv = 0.f;
            if (kk < SEQL) {
                size_t base = ((size_t)b * SEQL + kk) * DMODEL + h * DHEAD + d;
                kv = g_k[base];
                vv = g_v[base];
            }
            ks[i] = kv; vs[i] = vv;
        }
        if (threadIdx.x < 64) {
            int kk = kc + threadIdx.x;
            rels[threadIdx.x] = (kk < SEQL)
                ? ((kk == 0) ? -10 : ((kk == SEQL - 1) ? -11 : g_rel[b * SEQL + kk]))
                : -999;
        }
        __syncthreads();
        if (valid) {
            int jmax = min(64, SEQL - kc);
            for (int j = 0; j < jmax; j++) {
                if (rels[j] != myrel) continue;   // masked keys are exactly 0 in ref softmax
                float s = 0.f;
                #pragma unroll
                for (int d = 0; d < DHEAD; d++) s += q[d] * ks[j * DHEAD + d];
                float nm = fmaxf(m, s);
                float corr = __expf(m - nm);
                float p = __expf(s - nm);
                ssum = ssum * corr + p;
                #pragma unroll
                for (int d = 0; d < DHEAD; d++) o[d] = o[d] * corr + p * vs[j * DHEAD + d];
                m = nm;
            }
        }
    }
    if (valid) {
        float inv = 1.0f / ssum;   // every row attends at least to itself
        float* op = g_o + ((size_t)b * SEQL + l) * DMODEL + h * DHEAD;
        #pragma unroll
        for (int d = 0; d < DHEAD; d++) op[d] = o[d] * inv;
    }
}

// ---------------- output head: score[b,j] = x[b, 301+j, :] . W_out + b_out ----------------
__global__ void out_kernel(const float* __restrict__ W_out, const float* __restrict__ b_out,
                           float* __restrict__ out) {
    int b = blockIdx.y;
    int warp = threadIdx.x >> 5;
    int lane = threadIdx.x & 31;
    int j = blockIdx.x * 8 + warp;
    if (j >= NUM_VM) return;
    size_t row = (size_t)b * SEQL + NUM_PM + 1 + j;
    float acc = 0.f;
    #pragma unroll
    for (int d = lane; d < DMODEL; d += 32)
        acc += g_x[row * DMODEL + d] * W_out[d];
    #pragma unroll
    for (int o = 16; o > 0; o >>= 1) acc += __shfl_xor_sync(0xffffffffu, acc, o);
    if (lane == 0) out[(size_t)b * NUM_VM + j] = acc + b_out[0];
}

// ---------------- host launcher ----------------
extern "C" void kernel_launch(void* const* d_in, const int* in_sizes, int n_in,
                              void* d_out, int out_size) {
    const float* vm_states = (const float*)d_in[0];
    const float* num_step  = (const float*)d_in[1];
    const float* pm_states = (const float*)d_in[2];
    const float* W_pm = (const float*)d_in[3];
    const float* b_pm = (const float*)d_in[4];
    const float* W_vm = (const float*)d_in[5];
    const float* b_vm = (const float*)d_in[6];
    const float* critic = (const float*)d_in[7];
    const float* ln1_g = (const float*)d_in[8];
    const float* ln1_b = (const float*)d_in[9];
    const float* Wq = (const float*)d_in[10];
    const float* bq = (const float*)d_in[11];
    const float* Wk = (const float*)d_in[12];
    const float* bk = (const float*)d_in[13];
    const float* Wv = (const float*)d_in[14];
    const float* bv = (const float*)d_in[15];
    const float* Wo = (const float*)d_in[16];
    const float* bo = (const float*)d_in[17];
    const float* ln2_g = (const float*)d_in[18];
    const float* ln2_b = (const float*)d_in[19];
    const float* W1 = (const float*)d_in[20];
    const float* b1 = (const float*)d_in[21];
    const float* W2 = (const float*)d_in[22];
    const float* b2 = (const float*)d_in[23];
    const float* W_out = (const float*)d_in[24];
    const float* b_out = (const float*)d_in[25];
    float* out = (float*)d_out;

    void *px, *ph, *pq, *pk, *pv, *po, *pf;
    cudaGetSymbolAddress(&px, g_x);
    cudaGetSymbolAddress(&ph, g_h);
    cudaGetSymbolAddress(&pq, g_q);
    cudaGetSymbolAddress(&pk, g_k);
    cudaGetSymbolAddress(&pv, g_v);
    cudaGetSymbolAddress(&po, g_o);
    cudaGetSymbolAddress(&pf, g_ffn);
    float* x = (float*)px;
    float* h = (float*)ph;
    float* q = (float*)pq;
    float* k = (float*)pk;
    float* v = (float*)pv;
    float* o = (float*)po;
    float* f = (float*)pf;

    embed_kernel<<<dim3(SEQL, BATCH), DMODEL>>>(vm_states, num_step, pm_states,
                                                W_pm, b_pm, W_vm, b_vm, critic);

    const int M = MROWS;
    const int gridM = (M + BM - 1) / BM;           // 163
    dim3 g256(DMODEL / BN, gridM);                 // N=256
    dim3 g1024(DFF / BN, gridM);                   // N=1024
    dim3 gattn((SEQL + 255) / 256, NHEAD, BATCH);  // (6,8,8)

    for (int l = 0; l < NLAYER; l++) {
        ln_kernel<<<M, DMODEL>>>(ln1_g + l * DMODEL, ln1_b + l * DMODEL);
        sgemm_kernel<<<g256, 256>>>(h, Wq + (size_t)l * DMODEL * DMODEL, bq + l * DMODEL,
                                    q, nullptr, M, DMODEL, DMODEL, 0);
        sgemm_kernel<<<g256, 256>>>(h, Wk + (size_t)l * DMODEL * DMODEL, bk + l * DMODEL,
                                    k, nullptr, M, DMODEL, DMODEL, 0);
        sgemm_kernel<<<g256, 256>>>(h, Wv + (size_t)l * DMODEL * DMODEL, bv + l * DMODEL,
                                    v, nullptr, M, DMODEL, DMODEL, 0);
        attn_kernel<<<gattn, 256>>>();
        sgemm_kernel<<<g256, 256>>>(o, Wo + (size_t)l * DMODEL * DMODEL, bo + l * DMODEL,
                                    x, x, M, DMODEL, DMODEL, 0);
        ln_kernel<<<M, DMODEL>>>(ln2_g + l * DMODEL, ln2_b + l * DMODEL);
        sgemm_kernel<<<g1024, 256>>>(h, W1 + (size_t)l * DMODEL * DFF, b1 + l * DFF,
                                     f, nullptr, M, DFF, DMODEL, 1);
        sgemm_kernel<<<g256, 256>>>(f, W2 + (size_t)l * DFF * DMODEL, b2 + l * DMODEL,
                                    x, x, M, DMODEL, DFF, 0);
    }

    out_kernel<<<dim3((NUM_VM + 7) / 8, BATCH), 256>>>(W_out, b_out, out);
}

// round 2
// speedup vs baseline: 1.8768x; 1.8768x over previous
#include <cuda_runtime.h>
#include <cstdint>

#define BATCH 8
#define NUM_PM 300
#define NUM_VM 1000
#define PM_COV 8
#define DMODEL 256
#define NHEAD 8
#define DHEAD 32
#define DFF 1024
#define NLAYER 3
#define SEQL (NUM_PM + NUM_VM + 2)   // 1302
#define MROWS (BATCH * SEQL)          // 10416

// ---------------- static scratch (no allocation allowed) ----------------
__device__ float g_x[MROWS * DMODEL];
__device__ float g_h[MROWS * DMODEL];
__device__ float g_q[MROWS * DMODEL];
__device__ float g_k[MROWS * DMODEL];
__device__ float g_v[MROWS * DMODEL];
__device__ float g_o[MROWS * DMODEL];
__device__ float g_ffn[MROWS * DFF];
__device__ int   g_rel[MROWS];

// ---------------- embed + rel ----------------
__global__ void embed_kernel(const float* __restrict__ vm_states,
                             const float* __restrict__ num_step,
                             const float* __restrict__ pm_states,
                             const float* __restrict__ W_pm, const float* __restrict__ b_pm,
                             const float* __restrict__ W_vm, const float* __restrict__ b_vm,
                             const float* __restrict__ critic) {
    int b = blockIdx.y;
    int l = blockIdx.x;
    int d = threadIdx.x;
    float val;
    if (l == 0) {
        val = num_step[b];
    } else if (l <= NUM_PM) {
        const float* pm = pm_states + ((size_t)b * NUM_PM + (l - 1)) * PM_COV;
        float acc = b_pm[d];
        #pragma unroll
        for (int c = 0; c < PM_COV; c++) acc += pm[c] * W_pm[c * DMODEL + d];
        val = acc;
    } else if (l <= NUM_PM + NUM_VM) {
        const float* vm = vm_states + ((size_t)b * NUM_VM + (l - 1 - NUM_PM)) * 7;
        float acc = b_vm[d];
        #pragma unroll
        for (int c = 0; c < 6; c++) acc += vm[c] * W_vm[c * DMODEL + d];
        val = acc;
    } else {
        val = critic[d];
    }
    g_x[((size_t)b * SEQL + l) * DMODEL + d] = val;
    if (d == 0) {
        int r = -100;
        if (l >= 1 && l <= NUM_PM) r = l - 1;
        else if (l > NUM_PM && l < SEQL - 1)
            r = (int)vm_states[((size_t)b * NUM_VM + (l - 1 - NUM_PM)) * 7 + 6];
        g_rel[b * SEQL + l] = r;
    }
}

// ---------------- layernorm (row of 256) ----------------
__global__ void ln_kernel(const float* __restrict__ gamma, const float* __restrict__ beta) {
    int row = blockIdx.x;
    int d = threadIdx.x;
    float v = g_x[(size_t)row * DMODEL + d];
    __shared__ float red[8];
    __shared__ float bc_mean, bc_var;
    float s = v;
    #pragma unroll
    for (int o = 16; o > 0; o >>= 1) s += __shfl_xor_sync(0xffffffffu, s, o);
    if ((d & 31) == 0) red[d >> 5] = s;
    __syncthreads();
    if (d == 0) {
        float t = 0.f;
        #pragma unroll
        for (int i = 0; i < 8; i++) t += red[i];
        bc_mean = t * (1.0f / DMODEL);
    }
    __syncthreads();
    float mean = bc_mean;
    float c = v - mean;
    float cs = c * c;
    #pragma unroll
    for (int o = 16; o > 0; o >>= 1) cs += __shfl_xor_sync(0xffffffffu, cs, o);
    if ((d & 31) == 0) red[d >> 5] = cs;
    __syncthreads();
    if (d == 0) {
        float t = 0.f;
        #pragma unroll
        for (int i = 0; i < 8; i++) t += red[i];
        bc_var = t * (1.0f / DMODEL);
    }
    __syncthreads();
    float r = rsqrtf(bc_var + 1e-5f);
    g_h[(size_t)row * DMODEL + d] = c * r * gamma[d] + beta[d];
}

// ---------------- GELU (tanh approximation, matches jax.nn.gelu default) ----------------
__device__ __forceinline__ float gelu_f(float x) {
    float x3 = x * x * x;
    float t = tanhf(0.7978845608028654f * (x + 0.044715f * x3));
    return 0.5f * x * (1.0f + t);
}

// ================= tf32 tensor-core GEMM =================
// C[M,N] = A[M,K] @ W[K,N] + bias (+res) (opt gelu)
// BM=128, BN=64, BK=32; 256 threads = 8 warps (4 x 2), warp tile 32x32.
#define BMt 128
#define BNt 64
#define BKt 32
#define ASTRIDE 36               // floats per A smem row (16B-aligned: 144B)
#define BSTRIDE 72               // floats per B smem row (288B)
#define A_STAGE (BMt * ASTRIDE)  // 4608 floats
#define B_STAGE (BKt * BSTRIDE)  // 2304 floats
#define STAGEF  (A_STAGE + B_STAGE)
#define GEMM_SMEM (2 * STAGEF * 4)

__device__ __forceinline__ void cp16(float* dst, const void* src, int sz) {
    uint32_t d = (uint32_t)__cvta_generic_to_shared(dst);
    asm volatile("cp.async.cg.shared.global [%0], [%1], 16, %2;\n" :: "r"(d), "l"(src), "r"(sz));
}
__device__ __forceinline__ uint32_t f2tf32(float f) {
    uint32_t u;
    asm("cvt.rna.tf32.f32 %0, %1;\n" : "=r"(u) : "f"(f));
    return u;
}

__global__ void gemm_tf32(const float* __restrict__ A, const float* __restrict__ W,
                          const float* __restrict__ bias, float* __restrict__ C,
                          const float* __restrict__ res,
                          int M, int N, int K, int act) {
    extern __shared__ float sm[];
    const int tid = threadIdx.x;
    const int m0 = blockIdx.y * BMt;
    const int n0 = blockIdx.x * BNt;
    const int lane = tid & 31;
    const int warp = tid >> 5;
    const int wm = warp >> 1;          // 0..3
    const int wn = warp & 1;           // 0..1
    const int lq = lane >> 2;          // groupID 0..7
    const int lr = lane & 3;           // threadInGroup 0..3

    float c[2][4][4];
    #pragma unroll
    for (int i = 0; i < 2; i++)
        #pragma unroll
        for (int j = 0; j < 4; j++)
            #pragma unroll
            for (int p = 0; p < 4; p++) c[i][j][p] = 0.f;

    auto loadStage = [&](int stage, int kt) {
        float* As = sm + stage * STAGEF;
        float* Bs = As + A_STAGE;
        int gk = kt * BKt;
        #pragma unroll
        for (int p = 0; p < 4; p++) {
            int idx = tid + p * 256;
            int m = idx >> 3, k4 = idx & 7;
            int gm = m0 + m;
            int ok = (gm < M) ? 16 : 0;
            int gmc = (gm < M) ? gm : (M - 1);
            cp16(As + m * ASTRIDE + k4 * 4, A + (size_t)gmc * K + gk + k4 * 4, ok);
        }
        #pragma unroll
        for (int p = 0; p < 2; p++) {
            int idx = tid + p * 256;
            int k = idx >> 4, n4 = idx & 15;
            cp16(Bs + k * BSTRIDE + n4 * 4, W + (size_t)(gk + k) * N + n0 + n4 * 4, 16);
        }
    };

    auto computeStage = [&](int stage) {
        float* As = sm + stage * STAGEF;
        float* Bs = As + A_STAGE;
        #pragma unroll
        for (int kk = 0; kk < BKt; kk += 8) {
            uint32_t af[2][4], bf[4][2];
            #pragma unroll
            for (int tm = 0; tm < 2; tm++) {
                const float* ap = As + (wm * 32 + tm * 16 + lq) * ASTRIDE + kk + lr;
                af[tm][0] = f2tf32(ap[0]);
                af[tm][1] = f2tf32(ap[8 * ASTRIDE]);
                af[tm][2] = f2tf32(ap[4]);
                af[tm][3] = f2tf32(ap[8 * ASTRIDE + 4]);
            }
            #pragma unroll
            for (int tn = 0; tn < 4; tn++) {
                const float* bp = Bs + (kk + lr) * BSTRIDE + wn * 32 + tn * 8 + lq;
                bf[tn][0] = f2tf32(bp[0]);
                bf[tn][1] = f2tf32(bp[4 * BSTRIDE]);
            }
            #pragma unroll
            for (int tm = 0; tm < 2; tm++)
                #pragma unroll
                for (int tn = 0; tn < 4; tn++) {
                    asm volatile(
                        "mma.sync.aligned.m16n8k8.row.col.f32.tf32.tf32.f32 "
                        "{%0,%1,%2,%3}, {%4,%5,%6,%7}, {%8,%9}, {%0,%1,%2,%3};\n"
                        : "+f"(c[tm][tn][0]), "+f"(c[tm][tn][1]),
                          "+f"(c[tm][tn][2]), "+f"(c[tm][tn][3])
                        : "r"(af[tm][0]), "r"(af[tm][1]), "r"(af[tm][2]), "r"(af[tm][3]),
                          "r"(bf[tn][0]), "r"(bf[tn][1]));
                }
        }
    };

    const int KT = K / BKt;
    loadStage(0, 0);
    asm volatile("cp.async.commit_group;\n");
    int buf = 0;
    for (int kt = 0; kt < KT; kt++) {
        if (kt + 1 < KT) {
            loadStage(buf ^ 1, kt + 1);
            asm volatile("cp.async.commit_group;\n");
            asm volatile("cp.async.wait_group 1;\n");
        } else {
            asm volatile("cp.async.wait_group 0;\n");
        }
        __syncthreads();
        computeStage(buf);
        __syncthreads();
        buf ^= 1;
    }

    // epilogue
    #pragma unroll
    for (int tm = 0; tm < 2; tm++) {
        #pragma unroll
        for (int tn = 0; tn < 4; tn++) {
            int row0 = m0 + wm * 32 + tm * 16 + lq;
            int col = n0 + wn * 32 + tn * 8 + 2 * lr;
            #pragma unroll
            for (int half = 0; half < 2; half++) {
                int r = row0 + half * 8;
                if (r < M) {
                    float v0 = c[tm][tn][half * 2 + 0] + bias[col];
                    float v1 = c[tm][tn][half * 2 + 1] + bias[col + 1];
                    if (res) { v0 += res[(size_t)r * N + col]; v1 += res[(size_t)r * N + col + 1]; }
                    if (act) { v0 = gelu_f(v0); v1 = gelu_f(v1); }
                    C[(size_t)r * N + col] = v0;
                    C[(size_t)r * N + col + 1] = v1;
                }
            }
        }
    }
}

// ---------------- sparse masked attention (online softmax, skip masked keys) ----------------
__global__ void attn_kernel() {
    int b = blockIdx.z;
    int h = blockIdx.y;
    int l = blockIdx.x * 256 + threadIdx.x;
    bool valid = (l < SEQL);

    float q[DHEAD];
    float o[DHEAD];
    #pragma unroll
    for (int d = 0; d < DHEAD; d++) o[d] = 0.f;
    float m = -1e30f, ssum = 0.f;
    int myrel = -999;
    if (valid) {
        const float* qp = g_q + ((size_t)b * SEQL + l) * DMODEL + h * DHEAD;
        #pragma unroll
        for (int d = 0; d < DHEAD; d++) q[d] = qp[d] * 0.17677669529663687f; // 1/sqrt(32)
        myrel = (l == 0) ? -10 : ((l == SEQL - 1) ? -11 : g_rel[b * SEQL + l]);
    }

    __shared__ float ks[64 * DHEAD];
    __shared__ float vs[64 * DHEAD];
    __shared__ int rels[64];

    for (int kc = 0; kc < SEQL; kc += 64) {
        __syncthreads();
        for (int i = threadIdx.x; i < 64 * DHEAD; i += 256) {
            int j = i >> 5, d = i & 31;
            int kk = kc + j;
            float kv = 0.f, vv = 0.f;
            if (kk < SEQL) {
                size_t base = ((size_t)b * SEQL + kk) * DMODEL + h * DHEAD + d;
                kv = g_k[base];
                vv = g_v[base];
            }
            ks[i] = kv; vs[i] = vv;
        }
        if (threadIdx.x < 64) {
            int kk = kc + threadIdx.x;
            rels[threadIdx.x] = (kk < SEQL)
                ? ((kk == 0) ? -10 : ((kk == SEQL - 1) ? -11 : g_rel[b * SEQL + kk]))
                : -999;
        }
        __syncthreads();
        if (valid) {
            int jmax = min(64, SEQL - kc);
            for (int j = 0; j < jmax; j++) {
                if (rels[j] != myrel) continue;   // masked keys are exactly 0 in ref softmax
                float s = 0.f;
                #pragma unroll
                for (int d = 0; d < DHEAD; d++) s += q[d] * ks[j * DHEAD + d];
                float nm = fmaxf(m, s);
                float corr = __expf(m - nm);
                float p = __expf(s - nm);
                ssum = ssum * corr + p;
                #pragma unroll
                for (int d = 0; d < DHEAD; d++) o[d] = o[d] * corr + p * vs[j * DHEAD + d];
                m = nm;
            }
        }
    }
    if (valid) {
        float inv = 1.0f / ssum;   // every row attends at least to itself
        float* op = g_o + ((size_t)b * SEQL + l) * DMODEL + h * DHEAD;
        #pragma unroll
        for (int d = 0; d < DHEAD; d++) op[d] = o[d] * inv;
    }
}

// ---------------- output head ----------------
__global__ void out_kernel(const float* __restrict__ W_out, const float* __restrict__ b_out,
                           float* __restrict__ out) {
    int b = blockIdx.y;
    int warp = threadIdx.x >> 5;
    int lane = threadIdx.x & 31;
    int j = blockIdx.x * 8 + warp;
    if (j >= NUM_VM) return;
    size_t row = (size_t)b * SEQL + NUM_PM + 1 + j;
    float acc = 0.f;
    #pragma unroll
    for (int d = lane; d < DMODEL; d += 32)
        acc += g_x[row * DMODEL + d] * W_out[d];
    #pragma unroll
    for (int o = 16; o > 0; o >>= 1) acc += __shfl_xor_sync(0xffffffffu, acc, o);
    if (lane == 0) out[(size_t)b * NUM_VM + j] = acc + b_out[0];
}

// ---------------- host launcher ----------------
extern "C" void kernel_launch(void* const* d_in, const int* in_sizes, int n_in,
                              void* d_out, int out_size) {
    const float* vm_states = (const float*)d_in[0];
    const float* num_step  = (const float*)d_in[1];
    const float* pm_states = (const float*)d_in[2];
    const float* W_pm = (const float*)d_in[3];
    const float* b_pm = (const float*)d_in[4];
    const float* W_vm = (const float*)d_in[5];
    const float* b_vm = (const float*)d_in[6];
    const float* critic = (const float*)d_in[7];
    const float* ln1_g = (const float*)d_in[8];
    const float* ln1_b = (const float*)d_in[9];
    const float* Wq = (const float*)d_in[10];
    const float* bq = (const float*)d_in[11];
    const float* Wk = (const float*)d_in[12];
    const float* bk = (const float*)d_in[13];
    const float* Wv = (const float*)d_in[14];
    const float* bv = (const float*)d_in[15];
    const float* Wo = (const float*)d_in[16];
    const float* bo = (const float*)d_in[17];
    const float* ln2_g = (const float*)d_in[18];
    const float* ln2_b = (const float*)d_in[19];
    const float* W1 = (const float*)d_in[20];
    const float* b1 = (const float*)d_in[21];
    const float* W2 = (const float*)d_in[22];
    const float* b2 = (const float*)d_in[23];
    const float* W_out = (const float*)d_in[24];
    const float* b_out = (const float*)d_in[25];
    float* out = (float*)d_out;

    void *px, *ph, *pq, *pk, *pv, *po, *pf;
    cudaGetSymbolAddress(&px, g_x);
    cudaGetSymbolAddress(&ph, g_h);
    cudaGetSymbolAddress(&pq, g_q);
    cudaGetSymbolAddress(&pk, g_k);
    cudaGetSymbolAddress(&pv, g_v);
    cudaGetSymbolAddress(&po, g_o);
    cudaGetSymbolAddress(&pf, g_ffn);
    float* x = (float*)px;
    float* h = (float*)ph;
    float* q = (float*)pq;
    float* k = (float*)pk;
    float* v = (float*)pv;
    float* o = (float*)po;
    float* f = (float*)pf;

    cudaFuncSetAttribute(gemm_tf32, cudaFuncAttributeMaxDynamicSharedMemorySize, GEMM_SMEM);

    embed_kernel<<<dim3(SEQL, BATCH), DMODEL>>>(vm_states, num_step, pm_states,
                                                W_pm, b_pm, W_vm, b_vm, critic);

    const int M = MROWS;
    const int gridM = (M + BMt - 1) / BMt;          // 82
    dim3 g256(DMODEL / BNt, gridM);                 // (4, 82)
    dim3 g1024(DFF / BNt, gridM);                   // (16, 82)
    dim3 gattn((SEQL + 255) / 256, NHEAD, BATCH);   // (6, 8, 8)

    for (int l = 0; l < NLAYER; l++) {
        ln_kernel<<<M, DMODEL>>>(ln1_g + l * DMODEL, ln1_b + l * DMODEL);
        gemm_tf32<<<g256, 256, GEMM_SMEM>>>(h, Wq + (size_t)l * DMODEL * DMODEL, bq + l * DMODEL,
                                            q, nullptr, M, DMODEL, DMODEL, 0);
        gemm_tf32<<<g256, 256, GEMM_SMEM>>>(h, Wk + (size_t)l * DMODEL * DMODEL, bk + l * DMODEL,
                                            k, nullptr, M, DMODEL, DMODEL, 0);
        gemm_tf32<<<g256, 256, GEMM_SMEM>>>(h, Wv + (size_t)l * DMODEL * DMODEL, bv + l * DMODEL,
                                            v, nullptr, M, DMODEL, DMODEL, 0);
        attn_kernel<<<gattn, 256>>>();
        gemm_tf32<<<g256, 256, GEMM_SMEM>>>(o, Wo + (size_t)l * DMODEL * DMODEL, bo + l * DMODEL,
                                            x, x, M, DMODEL, DMODEL, 0);
        ln_kernel<<<M, DMODEL>>>(ln2_g + l * DMODEL, ln2_b + l * DMODEL);
        gemm_tf32<<<g1024, 256, GEMM_SMEM>>>(h, W1 + (size_t)l * DMODEL * DFF, b1 + l * DFF,
                                             f, nullptr, M, DFF, DMODEL, 1);
        gemm_tf32<<<g256, 256, GEMM_SMEM>>>(f, W2 + (size_t)l * DFF * DMODEL, b2 + l * DMODEL,
                                            x, x, M, DMODEL, DFF, 0);
    }

    out_kernel<<<dim3((NUM_VM + 7) / 8, BATCH), 256>>>(W_out, b_out, out);
}

// round 3
// speedup vs baseline: 4.5326x; 2.4151x over previous
#include <cuda_runtime.h>
#include <cstdint>

#define BATCH 8
#define NUM_PM 300
#define NUM_VM 1000
#define PM_COV 8
#define DMODEL 256
#define NHEAD 8
#define DHEAD 32
#define DFF 1024
#define NLAYER 3
#define SEQL (NUM_PM + NUM_VM + 2)   // 1302
#define MROWS (BATCH * SEQL)          // 10416
#define CAP 64                        // max keys per rel group (avg 4.3, tail-safe)

// ---------------- static scratch (no allocation allowed) ----------------
__device__ float g_x[MROWS * DMODEL];
__device__ float g_h[MROWS * DMODEL];
__device__ float g_q[MROWS * DMODEL];
__device__ float g_k[MROWS * DMODEL];
__device__ float g_v[MROWS * DMODEL];
__device__ float g_o[MROWS * DMODEL];
__device__ float g_ffn[MROWS * DFF];
__device__ int   g_rel[MROWS];
__device__ int   g_cnt[BATCH * NUM_PM];
__device__ int   g_list[BATCH * NUM_PM * CAP];

// ---------------- embed + rel ----------------
__global__ void embed_kernel(const float* __restrict__ vm_states,
                             const float* __restrict__ num_step,
                             const float* __restrict__ pm_states,
                             const float* __restrict__ W_pm, const float* __restrict__ b_pm,
                             const float* __restrict__ W_vm, const float* __restrict__ b_vm,
                             const float* __restrict__ critic) {
    int b = blockIdx.y;
    int l = blockIdx.x;
    int d = threadIdx.x;
    float val;
    if (l == 0) {
        val = num_step[b];
    } else if (l <= NUM_PM) {
        const float* pm = pm_states + (b * NUM_PM + (l - 1)) * PM_COV;
        float acc = b_pm[d];
        #pragma unroll
        for (int c = 0; c < PM_COV; c++) acc += pm[c] * W_pm[c * DMODEL + d];
        val = acc;
    } else if (l <= NUM_PM + NUM_VM) {
        const float* vm = vm_states + (b * NUM_VM + (l - 1 - NUM_PM)) * 7;
        float acc = b_vm[d];
        #pragma unroll
        for (int c = 0; c < 6; c++) acc += vm[c] * W_vm[c * DMODEL + d];
        val = acc;
    } else {
        val = critic[d];
    }
    g_x[(b * SEQL + l) * DMODEL + d] = val;
    if (d == 0) {
        int r = -100;
        if (l >= 1 && l <= NUM_PM) r = l - 1;
        else if (l > NUM_PM && l < SEQL - 1)
            r = (int)vm_states[(b * NUM_VM + (l - 1 - NUM_PM)) * 7 + 6];
        g_rel[b * SEQL + l] = r;
    }
}

// ---------------- group list build (mask is layer-invariant) ----------------
__global__ void build_init() {
    int i = blockIdx.x * 256 + threadIdx.x;
    if (i >= BATCH * NUM_PM) return;
    int r = i % NUM_PM;
    g_cnt[i] = 1;
    g_list[i * CAP] = 1 + r;          // PM token index
}

__global__ void build_vm(const float* __restrict__ vm_states) {
    int i = blockIdx.x * 256 + threadIdx.x;
    if (i >= BATCH * NUM_VM) return;
    int b = i / NUM_VM, j = i % NUM_VM;
    int r = (int)vm_states[(b * NUM_VM + j) * 7 + 6];
    int p = atomicAdd(&g_cnt[b * NUM_PM + r], 1);
    if (p < CAP) g_list[(b * NUM_PM + r) * CAP + p] = NUM_PM + 1 + j;
}

// ---------------- layernorm: warp per row of 256 ----------------
__global__ void ln_kernel(const float* __restrict__ gamma, const float* __restrict__ beta) {
    int row = blockIdx.x * 8 + (threadIdx.x >> 5);
    if (row >= MROWS) return;
    int lane = threadIdx.x & 31;
    float v8[8];
    float s = 0.f;
    #pragma unroll
    for (int t = 0; t < 8; t++) {
        v8[t] = g_x[row * DMODEL + lane + 32 * t];
        s += v8[t];
    }
    #pragma unroll
    for (int o = 16; o > 0; o >>= 1) s += __shfl_xor_sync(0xffffffffu, s, o);
    float mean = s * (1.0f / DMODEL);
    float vs = 0.f;
    #pragma unroll
    for (int t = 0; t < 8; t++) { v8[t] -= mean; vs += v8[t] * v8[t]; }
    #pragma unroll
    for (int o = 16; o > 0; o >>= 1) vs += __shfl_xor_sync(0xffffffffu, vs, o);
    float r = rsqrtf(vs * (1.0f / DMODEL) + 1e-5f);
    #pragma unroll
    for (int t = 0; t < 8; t++)
        g_h[row * DMODEL + lane + 32 * t] = v8[t] * r * gamma[lane + 32 * t] + beta[lane + 32 * t];
}

// ---------------- GELU (tanh approximation, matches jax.nn.gelu default) ----------------
__device__ __forceinline__ float gelu_f(float x) {
    float x3 = x * x * x;
    float t = tanhf(0.7978845608028654f * (x + 0.044715f * x3));
    return 0.5f * x * (1.0f + t);
}

// ================= tf32 tensor-core GEMM =================
#define BMt 128
#define BNt 64
#define BKt 32
#define ASTRIDE 36
#define BSTRIDE 72
#define A_STAGE (BMt * ASTRIDE)
#define B_STAGE (BKt * BSTRIDE)
#define STAGEF  (A_STAGE + B_STAGE)
#define GEMM_SMEM (2 * STAGEF * 4)

__device__ __forceinline__ void cp16(float* dst, const void* src, int sz) {
    uint32_t d = (uint32_t)__cvta_generic_to_shared(dst);
    asm volatile("cp.async.cg.shared.global [%0], [%1], 16, %2;\n" :: "r"(d), "l"(src), "r"(sz));
}
__device__ __forceinline__ uint32_t f2tf32(float f) {
    uint32_t u;
    asm("cvt.rna.tf32.f32 %0, %1;\n" : "=r"(u) : "f"(f));
    return u;
}

// z-dim selects among up to 3 weight/bias/output sets (QKV fusion).
__global__ void gemm_tf32(const float* __restrict__ A,
                          const float* __restrict__ W0, const float* __restrict__ W1p,
                          const float* __restrict__ W2p,
                          const float* __restrict__ bias0, const float* __restrict__ bias1,
                          const float* __restrict__ bias2,
                          float* __restrict__ C0, float* __restrict__ C1p, float* __restrict__ C2p,
                          const float* __restrict__ res,
                          int M, int N, int K, int act) {
    const float* W    = (blockIdx.z == 0) ? W0    : (blockIdx.z == 1) ? W1p   : W2p;
    const float* bias = (blockIdx.z == 0) ? bias0 : (blockIdx.z == 1) ? bias1 : bias2;
    float* C          = (blockIdx.z == 0) ? C0    : (blockIdx.z == 1) ? C1p   : C2p;

    extern __shared__ float sm[];
    const int tid = threadIdx.x;
    const int m0 = blockIdx.y * BMt;
    const int n0 = blockIdx.x * BNt;
    const int lane = tid & 31;
    const int warp = tid >> 5;
    const int wm = warp >> 1;
    const int wn = warp & 1;
    const int lq = lane >> 2;
    const int lr = lane & 3;

    float c[2][4][4];
    #pragma unroll
    for (int i = 0; i < 2; i++)
        #pragma unroll
        for (int j = 0; j < 4; j++)
            #pragma unroll
            for (int p = 0; p < 4; p++) c[i][j][p] = 0.f;

    auto loadStage = [&](int stage, int kt) {
        float* As = sm + stage * STAGEF;
        float* Bs = As + A_STAGE;
        int gk = kt * BKt;
        #pragma unroll
        for (int p = 0; p < 4; p++) {
            int idx = tid + p * 256;
            int m = idx >> 3, k4 = idx & 7;
            int gm = m0 + m;
            int ok = (gm < M) ? 16 : 0;
            int gmc = (gm < M) ? gm : (M - 1);
            cp16(As + m * ASTRIDE + k4 * 4, A + gmc * K + gk + k4 * 4, ok);
        }
        #pragma unroll
        for (int p = 0; p < 2; p++) {
            int idx = tid + p * 256;
            int k = idx >> 4, n4 = idx & 15;
            cp16(Bs + k * BSTRIDE + n4 * 4, W + (gk + k) * N + n0 + n4 * 4, 16);
        }
    };

    auto computeStage = [&](int stage) {
        float* As = sm + stage * STAGEF;
        float* Bs = As + A_STAGE;
        #pragma unroll
        for (int kk = 0; kk < BKt; kk += 8) {
            uint32_t af[2][4], bf[4][2];
            #pragma unroll
            for (int tm = 0; tm < 2; tm++) {
                const float* ap = As + (wm * 32 + tm * 16 + lq) * ASTRIDE + kk + lr;
                af[tm][0] = f2tf32(ap[0]);
                af[tm][1] = f2tf32(ap[8 * ASTRIDE]);
                af[tm][2] = f2tf32(ap[4]);
                af[tm][3] = f2tf32(ap[8 * ASTRIDE + 4]);
            }
            #pragma unroll
            for (int tn = 0; tn < 4; tn++) {
                const float* bp = Bs + (kk + lr) * BSTRIDE + wn * 32 + tn * 8 + lq;
                bf[tn][0] = f2tf32(bp[0]);
                bf[tn][1] = f2tf32(bp[4 * BSTRIDE]);
            }
            #pragma unroll
            for (int tm = 0; tm < 2; tm++)
                #pragma unroll
                for (int tn = 0; tn < 4; tn++) {
                    asm volatile(
                        "mma.sync.aligned.m16n8k8.row.col.f32.tf32.tf32.f32 "
                        "{%0,%1,%2,%3}, {%4,%5,%6,%7}, {%8,%9}, {%0,%1,%2,%3};\n"
                        : "+f"(c[tm][tn][0]), "+f"(c[tm][tn][1]),
                          "+f"(c[tm][tn][2]), "+f"(c[tm][tn][3])
                        : "r"(af[tm][0]), "r"(af[tm][1]), "r"(af[tm][2]), "r"(af[tm][3]),
                          "r"(bf[tn][0]), "r"(bf[tn][1]));
                }
        }
    };

    const int KT = K / BKt;
    loadStage(0, 0);
    asm volatile("cp.async.commit_group;\n");
    int buf = 0;
    for (int kt = 0; kt < KT; kt++) {
        if (kt + 1 < KT) {
            loadStage(buf ^ 1, kt + 1);
            asm volatile("cp.async.commit_group;\n");
            asm volatile("cp.async.wait_group 1;\n");
        } else {
            asm volatile("cp.async.wait_group 0;\n");
        }
        __syncthreads();
        computeStage(buf);
        __syncthreads();
        buf ^= 1;
    }

    #pragma unroll
    for (int tm = 0; tm < 2; tm++) {
        #pragma unroll
        for (int tn = 0; tn < 4; tn++) {
            int row0 = m0 + wm * 32 + tm * 16 + lq;
            int col = n0 + wn * 32 + tn * 8 + 2 * lr;
            #pragma unroll
            for (int half = 0; half < 2; half++) {
                int r = row0 + half * 8;
                if (r < M) {
                    float v0 = c[tm][tn][half * 2 + 0] + bias[col];
                    float v1 = c[tm][tn][half * 2 + 1] + bias[col + 1];
                    if (res) { v0 += res[r * N + col]; v1 += res[r * N + col + 1]; }
                    if (act) { v0 = gelu_f(v0); v1 = gelu_f(v1); }
                    C[r * N + col] = v0;
                    C[r * N + col + 1] = v1;
                }
            }
        }
    }
}

// ---------------- sparse attention v2: warp per (b, query), group lists ----------------
__global__ void attn_kernel() {
    int gw = blockIdx.x * 8 + (threadIdx.x >> 5);
    if (gw >= BATCH * SEQL) return;
    int b = gw / SEQL;
    int l = gw - b * SEQL;
    int lane = threadIdx.x & 31;
    int row = b * SEQL + l;

    if (l == 0 || l == SEQL - 1) {
        // self-only: softmax over one element -> output = V row
        #pragma unroll
        for (int t = 0; t < 8; t++)
            g_o[row * DMODEL + lane + 32 * t] = g_v[row * DMODEL + lane + 32 * t];
        return;
    }

    int r = g_rel[row];
    int cnt = g_cnt[b * NUM_PM + r];
    if (cnt > CAP) cnt = CAP;
    const int* lst = g_list + (b * NUM_PM + r) * CAP;

    const float scale = 0.17677669529663687f;   // 1/sqrt(32)
    float q8[8], o8[8], mx[8], sum[8];
    #pragma unroll
    for (int h = 0; h < 8; h++) {
        q8[h] = g_q[row * DMODEL + lane + 32 * h] * scale;
        o8[h] = 0.f; mx[h] = -1e30f; sum[h] = 0.f;
    }

    for (int i = 0; i < cnt; i++) {
        int krow = b * SEQL + lst[i];
        float k8[8], v8[8];
        #pragma unroll
        for (int t = 0; t < 8; t++) {
            k8[t] = g_k[krow * DMODEL + lane + 32 * t];
            v8[t] = g_v[krow * DMODEL + lane + 32 * t];
        }
        #pragma unroll
        for (int h = 0; h < 8; h++) {
            float d = q8[h] * k8[h];
            #pragma unroll
            for (int o = 16; o > 0; o >>= 1) d += __shfl_xor_sync(0xffffffffu, d, o);
            float nm = fmaxf(mx[h], d);
            float corr = __expf(mx[h] - nm);
            float p = __expf(d - nm);
            sum[h] = sum[h] * corr + p;
            o8[h] = o8[h] * corr + p * v8[h];
            mx[h] = nm;
        }
    }
    #pragma unroll
    for (int h = 0; h < 8; h++)
        g_o[row * DMODEL + lane + 32 * h] = o8[h] / sum[h];
}

// ---------------- output head ----------------
__global__ void out_kernel(const float* __restrict__ W_out, const float* __restrict__ b_out,
                           float* __restrict__ out) {
    int b = blockIdx.y;
    int warp = threadIdx.x >> 5;
    int lane = threadIdx.x & 31;
    int j = blockIdx.x * 8 + warp;
    if (j >= NUM_VM) return;
    int row = b * SEQL + NUM_PM + 1 + j;
    float acc = 0.f;
    #pragma unroll
    for (int d = lane; d < DMODEL; d += 32)
        acc += g_x[row * DMODEL + d] * W_out[d];
    #pragma unroll
    for (int o = 16; o > 0; o >>= 1) acc += __shfl_xor_sync(0xffffffffu, acc, o);
    if (lane == 0) out[b * NUM_VM + j] = acc + b_out[0];
}

// ---------------- host launcher ----------------
extern "C" void kernel_launch(void* const* d_in, const int* in_sizes, int n_in,
                              void* d_out, int out_size) {
    const float* vm_states = (const float*)d_in[0];
    const float* num_step  = (const float*)d_in[1];
    const float* pm_states = (const float*)d_in[2];
    const float* W_pm = (const float*)d_in[3];
    const float* b_pm = (const float*)d_in[4];
    const float* W_vm = (const float*)d_in[5];
    const float* b_vm = (const float*)d_in[6];
    const float* critic = (const float*)d_in[7];
    const float* ln1_g = (const float*)d_in[8];
    const float* ln1_b = (const float*)d_in[9];
    const float* Wq = (const float*)d_in[10];
    const float* bq = (const float*)d_in[11];
    const float* Wk = (const float*)d_in[12];
    const float* bk = (const float*)d_in[13];
    const float* Wv = (const float*)d_in[14];
    const float* bv = (const float*)d_in[15];
    const float* Wo = (const float*)d_in[16];
    const float* bo = (const float*)d_in[17];
    const float* ln2_g = (const float*)d_in[18];
    const float* ln2_b = (const float*)d_in[19];
    const float* W1 = (const float*)d_in[20];
    const float* b1 = (const float*)d_in[21];
    const float* W2 = (const float*)d_in[22];
    const float* b2 = (const float*)d_in[23];
    const float* W_out = (const float*)d_in[24];
    const float* b_out = (const float*)d_in[25];
    float* out = (float*)d_out;

    void *px, *ph, *pq, *pk, *pv, *po, *pf;
    cudaGetSymbolAddress(&px, g_x);
    cudaGetSymbolAddress(&ph, g_h);
    cudaGetSymbolAddress(&pq, g_q);
    cudaGetSymbolAddress(&pk, g_k);
    cudaGetSymbolAddress(&pv, g_v);
    cudaGetSymbolAddress(&po, g_o);
    cudaGetSymbolAddress(&pf, g_ffn);
    float* x = (float*)px;
    float* h = (float*)ph;
    float* q = (float*)pq;
    float* k = (float*)pk;
    float* v = (float*)pv;
    float* o = (float*)po;
    float* f = (float*)pf;

    cudaFuncSetAttribute(gemm_tf32, cudaFuncAttributeMaxDynamicSharedMemorySize, GEMM_SMEM);

    embed_kernel<<<dim3(SEQL, BATCH), DMODEL>>>(vm_states, num_step, pm_states,
                                                W_pm, b_pm, W_vm, b_vm, critic);
    build_init<<<(BATCH * NUM_PM + 255) / 256, 256>>>();
    build_vm<<<(BATCH * NUM_VM + 255) / 256, 256>>>(vm_states);

    const int M = MROWS;
    const int gridM = (M + BMt - 1) / BMt;              // 82
    dim3 gQKV(DMODEL / BNt, gridM, 3);                  // (4, 82, 3)
    dim3 g256(DMODEL / BNt, gridM, 1);
    dim3 g1024(DFF / BNt, gridM, 1);
    dim3 gln((MROWS + 7) / 8);
    dim3 gattn((BATCH * SEQL + 7) / 8);

    for (int l = 0; l < NLAYER; l++) {
        ln_kernel<<<gln, 256>>>(ln1_g + l * DMODEL, ln1_b + l * DMODEL);
        gemm_tf32<<<gQKV, 256, GEMM_SMEM>>>(h,
            Wq + l * DMODEL * DMODEL, Wk + l * DMODEL * DMODEL, Wv + l * DMODEL * DMODEL,
            bq + l * DMODEL, bk + l * DMODEL, bv + l * DMODEL,
            q, k, v, nullptr, M, DMODEL, DMODEL, 0);
        attn_kernel<<<gattn, 256>>>();
        gemm_tf32<<<g256, 256, GEMM_SMEM>>>(o,
            Wo + l * DMODEL * DMODEL, Wo + l * DMODEL * DMODEL, Wo + l * DMODEL * DMODEL,
            bo + l * DMODEL, bo + l * DMODEL, bo + l * DMODEL,
            x, x, x, x, M, DMODEL, DMODEL, 0);
        ln_kernel<<<gln, 256>>>(ln2_g + l * DMODEL, ln2_b + l * DMODEL);
        gemm_tf32<<<g1024, 256, GEMM_SMEM>>>(h,
            W1 + l * DMODEL * DFF, W1 + l * DMODEL * DFF, W1 + l * DMODEL * DFF,
            b1 + l * DFF, b1 + l * DFF, b1 + l * DFF,
            f, f, f, nullptr, M, DFF, DMODEL, 1);
        gemm_tf32<<<g256, 256, GEMM_SMEM>>>(f,
            W2 + l * DFF * DMODEL, W2 + l * DFF * DMODEL, W2 + l * DFF * DMODEL,
            b2 + l * DMODEL, b2 + l * DMODEL, b2 + l * DMODEL,
            x, x, x, x, M, DMODEL, DFF, 0);
    }

    out_kernel<<<dim3((NUM_VM + 7) / 8, BATCH), 256>>>(W_out, b_out, out);
}

// round 4
// speedup vs baseline: 4.5915x; 1.0130x over previous
#include <cuda_runtime.h>
#include <cstdint>

#define BATCH 8
#define NUM_PM 300
#define NUM_VM 1000
#define PM_COV 8
#define DMODEL 256
#define NHEAD 8
#define DHEAD 32
#define DFF 1024
#define NLAYER 3
#define SEQL (NUM_PM + NUM_VM + 2)   // 1302
#define MROWS (BATCH * SEQL)          // 10416
#define CAP 64

// ---------------- static scratch ----------------
__device__ float g_x[MROWS * DMODEL];
__device__ float g_h[MROWS * DMODEL];
__device__ float g_q[MROWS * DMODEL];
__device__ float g_k[MROWS * DMODEL];
__device__ float g_v[MROWS * DMODEL];
__device__ float g_o[MROWS * DMODEL];
__device__ float g_ffn[MROWS * DFF];
__device__ int   g_rel[MROWS];
__device__ int   g_cnt[BATCH * NUM_PM];
__device__ int   g_list[BATCH * NUM_PM * CAP];
// pre-rounded (tf32) weights
__device__ float g_Wq[NLAYER * DMODEL * DMODEL];
__device__ float g_Wk[NLAYER * DMODEL * DMODEL];
__device__ float g_Wv[NLAYER * DMODEL * DMODEL];
__device__ float g_Wo[NLAYER * DMODEL * DMODEL];
__device__ float g_W1r[NLAYER * DMODEL * DFF];
__device__ float g_W2r[NLAYER * DFF * DMODEL];

__device__ __forceinline__ uint32_t f2tf32(float f) {
    uint32_t u;
    asm("cvt.rna.tf32.f32 %0, %1;\n" : "=r"(u) : "f"(f));
    return u;
}
__device__ __forceinline__ float roundtf(float f) { return __uint_as_float(f2tf32(f)); }

// ---------------- round-copy weights (float4) ----------------
__global__ void roundcopy(const float* __restrict__ src, float* __restrict__ dst, int n4) {
    int i = blockIdx.x * 256 + threadIdx.x;
    if (i >= n4) return;
    float4 v = ((const float4*)src)[i];
    v.x = roundtf(v.x); v.y = roundtf(v.y); v.z = roundtf(v.z); v.w = roundtf(v.w);
    ((float4*)dst)[i] = v;
}

// ---------------- embed + rel ----------------
__global__ void embed_kernel(const float* __restrict__ vm_states,
                             const float* __restrict__ num_step,
                             const float* __restrict__ pm_states,
                             const float* __restrict__ W_pm, const float* __restrict__ b_pm,
                             const float* __restrict__ W_vm, const float* __restrict__ b_vm,
                             const float* __restrict__ critic) {
    int b = blockIdx.y;
    int l = blockIdx.x;
    int d = threadIdx.x;
    float val;
    if (l == 0) {
        val = num_step[b];
    } else if (l <= NUM_PM) {
        const float* pm = pm_states + (b * NUM_PM + (l - 1)) * PM_COV;
        float acc = b_pm[d];
        #pragma unroll
        for (int c = 0; c < PM_COV; c++) acc += pm[c] * W_pm[c * DMODEL + d];
        val = acc;
    } else if (l <= NUM_PM + NUM_VM) {
        const float* vm = vm_states + (b * NUM_VM + (l - 1 - NUM_PM)) * 7;
        float acc = b_vm[d];
        #pragma unroll
        for (int c = 0; c < 6; c++) acc += vm[c] * W_vm[c * DMODEL + d];
        val = acc;
    } else {
        val = critic[d];
    }
    g_x[(b * SEQL + l) * DMODEL + d] = val;
    if (d == 0) {
        int r = -100;
        if (l >= 1 && l <= NUM_PM) r = l - 1;
        else if (l > NUM_PM && l < SEQL - 1)
            r = (int)vm_states[(b * NUM_VM + (l - 1 - NUM_PM)) * 7 + 6];
        g_rel[b * SEQL + l] = r;
    }
}

// ---------------- group list build ----------------
__global__ void build_init() {
    int i = blockIdx.x * 256 + threadIdx.x;
    if (i >= BATCH * NUM_PM) return;
    int r = i % NUM_PM;
    g_cnt[i] = 1;
    g_list[i * CAP] = 1 + r;
}

__global__ void build_vm(const float* __restrict__ vm_states) {
    int i = blockIdx.x * 256 + threadIdx.x;
    if (i >= BATCH * NUM_VM) return;
    int b = i / NUM_VM, j = i % NUM_VM;
    int r = (int)vm_states[(b * NUM_VM + j) * 7 + 6];
    int p = atomicAdd(&g_cnt[b * NUM_PM + r], 1);
    if (p < CAP) g_list[(b * NUM_PM + r) * CAP + p] = NUM_PM + 1 + j;
}

// ---------------- layernorm: warp per row, float4, tf32-rounded output ----------------
__global__ void ln_kernel(const float* __restrict__ gamma, const float* __restrict__ beta) {
    int row = blockIdx.x * 8 + (threadIdx.x >> 5);
    if (row >= MROWS) return;
    int lane = threadIdx.x & 31;
    const float4* xr = (const float4*)(g_x + row * DMODEL) + lane * 2;
    float4 a = xr[0], c4 = xr[1];
    float v8[8] = {a.x, a.y, a.z, a.w, c4.x, c4.y, c4.z, c4.w};
    float s = 0.f;
    #pragma unroll
    for (int t = 0; t < 8; t++) s += v8[t];
    #pragma unroll
    for (int o = 16; o > 0; o >>= 1) s += __shfl_xor_sync(0xffffffffu, s, o);
    float mean = s * (1.0f / DMODEL);
    float vs = 0.f;
    #pragma unroll
    for (int t = 0; t < 8; t++) { v8[t] -= mean; vs += v8[t] * v8[t]; }
    #pragma unroll
    for (int o = 16; o > 0; o >>= 1) vs += __shfl_xor_sync(0xffffffffu, vs, o);
    float r = rsqrtf(vs * (1.0f / DMODEL) + 1e-5f);
    const float4* gg = (const float4*)gamma + lane * 2;
    const float4* bb = (const float4*)beta + lane * 2;
    float4 g0 = gg[0], g1 = gg[1], b0 = bb[0], b1 = bb[1];
    float ge[8] = {g0.x, g0.y, g0.z, g0.w, g1.x, g1.y, g1.z, g1.w};
    float be[8] = {b0.x, b0.y, b0.z, b0.w, b1.x, b1.y, b1.z, b1.w};
    float o8[8];
    #pragma unroll
    for (int t = 0; t < 8; t++) o8[t] = roundtf(v8[t] * r * ge[t] + be[t]);
    float4* hr = (float4*)(g_h + row * DMODEL) + lane * 2;
    hr[0] = make_float4(o8[0], o8[1], o8[2], o8[3]);
    hr[1] = make_float4(o8[4], o8[5], o8[6], o8[7]);
}

// ---------------- GELU (tanh approx) ----------------
__device__ __forceinline__ float gelu_f(float x) {
    float x3 = x * x * x;
    float t = tanhf(0.7978845608028654f * (x + 0.044715f * x3));
    return 0.5f * x * (1.0f + t);
}

// ================= tf32 tensor-core GEMM (pre-rounded operands, no in-loop cvt) ========
// 128x128 block, 8 warps (2 x 4), warp tile 64x32, BK=32, 2-stage cp.async.
#define BMt 128
#define BNt 128
#define BKt 32
#define ASTRIDE 36
#define BSTRIDE 136
#define A_STAGE (BMt * ASTRIDE)     // 4608
#define B_STAGE (BKt * BSTRIDE)     // 4352
#define STAGEF  (A_STAGE + B_STAGE) // 8960
#define GEMM_SMEM (2 * STAGEF * 4)  // 71680 B

__device__ __forceinline__ void cp16(float* dst, const void* src, int sz) {
    uint32_t d = (uint32_t)__cvta_generic_to_shared(dst);
    asm volatile("cp.async.cg.shared.global [%0], [%1], 16, %2;\n" :: "r"(d), "l"(src), "r"(sz));
}

// z-dim selects among up to 3 weight/bias/output sets (QKV fusion).
__global__ void gemm_tf32(const float* __restrict__ A,
                          const float* __restrict__ W0, const float* __restrict__ W1p,
                          const float* __restrict__ W2p,
                          const float* __restrict__ bias0, const float* __restrict__ bias1,
                          const float* __restrict__ bias2,
                          float* __restrict__ C0, float* __restrict__ C1p, float* __restrict__ C2p,
                          const float* __restrict__ res,
                          int M, int N, int K, int act) {
    const float* W    = (blockIdx.z == 0) ? W0    : (blockIdx.z == 1) ? W1p   : W2p;
    const float* bias = (blockIdx.z == 0) ? bias0 : (blockIdx.z == 1) ? bias1 : bias2;
    float* C          = (blockIdx.z == 0) ? C0    : (blockIdx.z == 1) ? C1p   : C2p;

    extern __shared__ float sm[];
    const int tid = threadIdx.x;
    const int m0 = blockIdx.y * BMt;
    const int n0 = blockIdx.x * BNt;
    const int lane = tid & 31;
    const int warp = tid >> 5;
    const int wm = warp >> 2;          // 0..1
    const int wn = warp & 3;           // 0..3
    const int lq = lane >> 2;          // 0..7
    const int lr = lane & 3;           // 0..3

    float c[4][4][4];
    #pragma unroll
    for (int i = 0; i < 4; i++)
        #pragma unroll
        for (int j = 0; j < 4; j++)
            #pragma unroll
            for (int p = 0; p < 4; p++) c[i][j][p] = 0.f;

    auto loadStage = [&](int stage, int kt) {
        float* As = sm + stage * STAGEF;
        float* Bs = As + A_STAGE;
        int gk = kt * BKt;
        #pragma unroll
        for (int p = 0; p < 4; p++) {
            int idx = tid + p * 256;
            int m = idx >> 3, k4 = idx & 7;
            int gm = m0 + m;
            int ok = (gm < M) ? 16 : 0;
            int gmc = (gm < M) ? gm : (M - 1);
            cp16(As + m * ASTRIDE + k4 * 4, A + gmc * K + gk + k4 * 4, ok);
        }
        #pragma unroll
        for (int p = 0; p < 4; p++) {
            int idx = tid + p * 256;
            int k = idx >> 5, n4 = idx & 31;
            cp16(Bs + k * BSTRIDE + n4 * 4, W + (gk + k) * N + n0 + n4 * 4, 16);
        }
    };

    auto computeStage = [&](int stage) {
        float* As = sm + stage * STAGEF;
        float* Bs = As + A_STAGE;
        #pragma unroll
        for (int kk = 0; kk < BKt; kk += 8) {
            uint32_t af[4][4], bf[4][2];
            #pragma unroll
            for (int tm = 0; tm < 4; tm++) {
                const float* ap = As + (wm * 64 + tm * 16 + lq) * ASTRIDE + kk + lr;
                af[tm][0] = __float_as_uint(ap[0]);
                af[tm][1] = __float_as_uint(ap[8 * ASTRIDE]);
                af[tm][2] = __float_as_uint(ap[4]);
                af[tm][3] = __float_as_uint(ap[8 * ASTRIDE + 4]);
            }
            #pragma unroll
            for (int tn = 0; tn < 4; tn++) {
                const float* bp = Bs + (kk + lr) * BSTRIDE + wn * 32 + tn * 8 + lq;
                bf[tn][0] = __float_as_uint(bp[0]);
                bf[tn][1] = __float_as_uint(bp[4 * BSTRIDE]);
            }
            #pragma unroll
            for (int tm = 0; tm < 4; tm++)
                #pragma unroll
                for (int tn = 0; tn < 4; tn++) {
                    asm volatile(
                        "mma.sync.aligned.m16n8k8.row.col.f32.tf32.tf32.f32 "
                        "{%0,%1,%2,%3}, {%4,%5,%6,%7}, {%8,%9}, {%0,%1,%2,%3};\n"
                        : "+f"(c[tm][tn][0]), "+f"(c[tm][tn][1]),
                          "+f"(c[tm][tn][2]), "+f"(c[tm][tn][3])
                        : "r"(af[tm][0]), "r"(af[tm][1]), "r"(af[tm][2]), "r"(af[tm][3]),
                          "r"(bf[tn][0]), "r"(bf[tn][1]));
                }
        }
    };

    const int KT = K / BKt;
    loadStage(0, 0);
    asm volatile("cp.async.commit_group;\n");
    int buf = 0;
    for (int kt = 0; kt < KT; kt++) {
        if (kt + 1 < KT) {
            loadStage(buf ^ 1, kt + 1);
            asm volatile("cp.async.commit_group;\n");
            asm volatile("cp.async.wait_group 1;\n");
        } else {
            asm volatile("cp.async.wait_group 0;\n");
        }
        __syncthreads();
        computeStage(buf);
        __syncthreads();
        buf ^= 1;
    }

    #pragma unroll
    for (int tm = 0; tm < 4; tm++) {
        #pragma unroll
        for (int tn = 0; tn < 4; tn++) {
            int row0 = m0 + wm * 64 + tm * 16 + lq;
            int col = n0 + wn * 32 + tn * 8 + 2 * lr;
            #pragma unroll
            for (int half = 0; half < 2; half++) {
                int r = row0 + half * 8;
                if (r < M) {
                    float v0 = c[tm][tn][half * 2 + 0] + bias[col];
                    float v1 = c[tm][tn][half * 2 + 1] + bias[col + 1];
                    if (res) { v0 += res[r * N + col]; v1 += res[r * N + col + 1]; }
                    if (act) { v0 = roundtf(gelu_f(v0)); v1 = roundtf(gelu_f(v1)); }
                    C[r * N + col] = v0;
                    C[r * N + col + 1] = v1;
                }
            }
        }
    }
}

// ---------------- sparse attention: warp per (b, query), tf32-rounded output ----------------
__global__ void attn_kernel() {
    int gw = blockIdx.x * 8 + (threadIdx.x >> 5);
    if (gw >= BATCH * SEQL) return;
    int b = gw / SEQL;
    int l = gw - b * SEQL;
    int lane = threadIdx.x & 31;
    int row = b * SEQL + l;

    if (l == 0 || l == SEQL - 1) {
        #pragma unroll
        for (int t = 0; t < 8; t++)
            g_o[row * DMODEL + lane + 32 * t] = roundtf(g_v[row * DMODEL + lane + 32 * t]);
        return;
    }

    int r = g_rel[row];
    int cnt = g_cnt[b * NUM_PM + r];
    if (cnt > CAP) cnt = CAP;
    const int* lst = g_list + (b * NUM_PM + r) * CAP;

    const float scale = 0.17677669529663687f;
    float q8[8], o8[8], mx[8], sum[8];
    #pragma unroll
    for (int h = 0; h < 8; h++) {
        q8[h] = g_q[row * DMODEL + lane + 32 * h] * scale;
        o8[h] = 0.f; mx[h] = -1e30f; sum[h] = 0.f;
    }

    for (int i = 0; i < cnt; i++) {
        int krow = b * SEQL + lst[i];
        float k8[8], v8[8];
        #pragma unroll
        for (int t = 0; t < 8; t++) {
            k8[t] = g_k[krow * DMODEL + lane + 32 * t];
            v8[t] = g_v[krow * DMODEL + lane + 32 * t];
        }
        #pragma unroll
        for (int h = 0; h < 8; h++) {
            float d = q8[h] * k8[h];
            #pragma unroll
            for (int o = 16; o > 0; o >>= 1) d += __shfl_xor_sync(0xffffffffu, d, o);
            float nm = fmaxf(mx[h], d);
            float corr = __expf(mx[h] - nm);
            float p = __expf(d - nm);
            sum[h] = sum[h] * corr + p;
            o8[h] = o8[h] * corr + p * v8[h];
            mx[h] = nm;
        }
    }
    #pragma unroll
    for (int h = 0; h < 8; h++)
        g_o[row * DMODEL + lane + 32 * h] = roundtf(o8[h] / sum[h]);
}

// ---------------- output head ----------------
__global__ void out_kernel(const float* __restrict__ W_out, const float* __restrict__ b_out,
                           float* __restrict__ out) {
    int b = blockIdx.y;
    int warp = threadIdx.x >> 5;
    int lane = threadIdx.x & 31;
    int j = blockIdx.x * 8 + warp;
    if (j >= NUM_VM) return;
    int row = b * SEQL + NUM_PM + 1 + j;
    float acc = 0.f;
    #pragma unroll
    for (int d = lane; d < DMODEL; d += 32)
        acc += g_x[row * DMODEL + d] * W_out[d];
    #pragma unroll
    for (int o = 16; o > 0; o >>= 1) acc += __shfl_xor_sync(0xffffffffu, acc, o);
    if (lane == 0) out[b * NUM_VM + j] = acc + b_out[0];
}

// ---------------- host launcher ----------------
extern "C" void kernel_launch(void* const* d_in, const int* in_sizes, int n_in,
                              void* d_out, int out_size) {
    const float* vm_states = (const float*)d_in[0];
    const float* num_step  = (const float*)d_in[1];
    const float* pm_states = (const float*)d_in[2];
    const float* W_pm = (const float*)d_in[3];
    const float* b_pm = (const float*)d_in[4];
    const float* W_vm = (const float*)d_in[5];
    const float* b_vm = (const float*)d_in[6];
    const float* critic = (const float*)d_in[7];
    const float* ln1_g = (const float*)d_in[8];
    const float* ln1_b = (const float*)d_in[9];
    const float* Wq = (const float*)d_in[10];
    const float* bq = (const float*)d_in[11];
    const float* Wk = (const float*)d_in[12];
    const float* bk = (const float*)d_in[13];
    const float* Wv = (const float*)d_in[14];
    const float* bv = (const float*)d_in[15];
    const float* Wo = (const float*)d_in[16];
    const float* bo = (const float*)d_in[17];
    const float* ln2_g = (const float*)d_in[18];
    const float* ln2_b = (const float*)d_in[19];
    const float* W1 = (const float*)d_in[20];
    const float* b1 = (const float*)d_in[21];
    const float* W2 = (const float*)d_in[22];
    const float* b2 = (const float*)d_in[23];
    const float* W_out = (const float*)d_in[24];
    const float* b_out = (const float*)d_in[25];
    float* out = (float*)d_out;

    void *ph, *pq, *pk, *pv, *po, *pf, *px;
    void *pWq, *pWk, *pWv, *pWo, *pW1, *pW2;
    cudaGetSymbolAddress(&px, g_x);
    cudaGetSymbolAddress(&ph, g_h);
    cudaGetSymbolAddress(&pq, g_q);
    cudaGetSymbolAddress(&pk, g_k);
    cudaGetSymbolAddress(&pv, g_v);
    cudaGetSymbolAddress(&po, g_o);
    cudaGetSymbolAddress(&pf, g_ffn);
    cudaGetSymbolAddress(&pWq, g_Wq);
    cudaGetSymbolAddress(&pWk, g_Wk);
    cudaGetSymbolAddress(&pWv, g_Wv);
    cudaGetSymbolAddress(&pWo, g_Wo);
    cudaGetSymbolAddress(&pW1, g_W1r);
    cudaGetSymbolAddress(&pW2, g_W2r);
    float* x = (float*)px;
    float* h = (float*)ph;
    float* q = (float*)pq;
    float* k = (float*)pk;
    float* v = (float*)pv;
    float* o = (float*)po;
    float* f = (float*)pf;
    float* rWq = (float*)pWq;
    float* rWk = (float*)pWk;
    float* rWv = (float*)pWv;
    float* rWo = (float*)pWo;
    float* rW1 = (float*)pW1;
    float* rW2 = (float*)pW2;

    cudaFuncSetAttribute(gemm_tf32, cudaFuncAttributeMaxDynamicSharedMemorySize, GEMM_SMEM);

    // pre-round all weights to tf32 (once per inference; ~4 us)
    const int NQ4 = NLAYER * DMODEL * DMODEL / 4;      // 49152
    const int NF4 = NLAYER * DMODEL * DFF / 4;         // 196608
    roundcopy<<<(NQ4 + 255) / 256, 256>>>(Wq, rWq, NQ4);
    roundcopy<<<(NQ4 + 255) / 256, 256>>>(Wk, rWk, NQ4);
    roundcopy<<<(NQ4 + 255) / 256, 256>>>(Wv, rWv, NQ4);
    roundcopy<<<(NQ4 + 255) / 256, 256>>>(Wo, rWo, NQ4);
    roundcopy<<<(NF4 + 255) / 256, 256>>>(W1, rW1, NF4);
    roundcopy<<<(NF4 + 255) / 256, 256>>>(W2, rW2, NF4);

    embed_kernel<<<dim3(SEQL, BATCH), DMODEL>>>(vm_states, num_step, pm_states,
                                                W_pm, b_pm, W_vm, b_vm, critic);
    build_init<<<(BATCH * NUM_PM + 255) / 256, 256>>>();
    build_vm<<<(BATCH * NUM_VM + 255) / 256, 256>>>(vm_states);

    const int M = MROWS;
    const int gridM = (M + BMt - 1) / BMt;              // 82
    dim3 gQKV(DMODEL / BNt, gridM, 3);                  // (2, 82, 3)
    dim3 g256(DMODEL / BNt, gridM, 1);                  // (2, 82)
    dim3 g1024(DFF / BNt, gridM, 1);                    // (8, 82)
    dim3 gln((MROWS + 7) / 8);
    dim3 gattn((BATCH * SEQL + 7) / 8);

    for (int l = 0; l < NLAYER; l++) {
        ln_kernel<<<gln, 256>>>(ln1_g + l * DMODEL, ln1_b + l * DMODEL);
        gemm_tf32<<<gQKV, 256, GEMM_SMEM>>>(h,
            rWq + l * DMODEL * DMODEL, rWk + l * DMODEL * DMODEL, rWv + l * DMODEL * DMODEL,
            bq + l * DMODEL, bk + l * DMODEL, bv + l * DMODEL,
            q, k, v, nullptr, M, DMODEL, DMODEL, 0);
        attn_kernel<<<gattn, 256>>>();
        gemm_tf32<<<g256, 256, GEMM_SMEM>>>(o,
            rWo + l * DMODEL * DMODEL, rWo + l * DMODEL * DMODEL, rWo + l * DMODEL * DMODEL,
            bo + l * DMODEL, bo + l * DMODEL, bo + l * DMODEL,
            x, x, x, x, M, DMODEL, DMODEL, 0);
        ln_kernel<<<gln, 256>>>(ln2_g + l * DMODEL, ln2_b + l * DMODEL);
        gemm_tf32<<<g1024, 256, GEMM_SMEM>>>(h,
            rW1 + l * DMODEL * DFF, rW1 + l * DMODEL * DFF, rW1 + l * DMODEL * DFF,
            b1 + l * DFF, b1 + l * DFF, b1 + l * DFF,
            f, f, f, nullptr, M, DFF, DMODEL, 1);
        gemm_tf32<<<g256, 256, GEMM_SMEM>>>(f,
            rW2 + l * DFF * DMODEL, rW2 + l * DFF * DMODEL, rW2 + l * DFF * DMODEL,
            b2 + l * DMODEL, b2 + l * DMODEL, b2 + l * DMODEL,
            x, x, x, x, M, DMODEL, DFF, 0);
    }

    out_kernel<<<dim3((NUM_VM + 7) / 8, BATCH), 256>>>(W_out, b_out, out);
}

// round 8
// speedup vs baseline: 6.4320x; 1.4009x over previous
#include <cuda_runtime.h>
#include <cuda_fp16.h>
#include <cstdint>

#define BATCH 8
#define NUM_PM 300
#define NUM_VM 1000
#define PM_COV 8
#define DMODEL 256
#define NHEAD 8
#define DHEAD 32
#define DFF 1024
#define NLAYER 3
#define SEQL (NUM_PM + NUM_VM + 2)   // 1302
#define MROWS (BATCH * SEQL)          // 10416
#define CAP 64

// ---------------- static scratch ----------------
__device__ float  g_x[MROWS * DMODEL];
__device__ __half g_h[MROWS * DMODEL];
__device__ float  g_q[MROWS * DMODEL];
__device__ float  g_k[MROWS * DMODEL];
__device__ float  g_v[MROWS * DMODEL];
__device__ __half g_o[MROWS * DMODEL];
__device__ __half g_ffn[MROWS * DFF];
__device__ int    g_rel[MROWS];
__device__ int    g_cnt[BATCH * NUM_PM];
__device__ int    g_list[BATCH * NUM_PM * CAP];
// transposed + fp16 weights, [N][K] K-major
__device__ __half g_Wqt[NLAYER * DMODEL * DMODEL];
__device__ __half g_Wkt[NLAYER * DMODEL * DMODEL];
__device__ __half g_Wvt[NLAYER * DMODEL * DMODEL];
__device__ __half g_Wot[NLAYER * DMODEL * DMODEL];
__device__ __half g_W1t[NLAYER * DMODEL * DFF];
__device__ __half g_W2t[NLAYER * DFF * DMODEL];

__device__ __forceinline__ uint32_t h2_u32(__half2 h) {
    union { __half2 h2; uint32_t u; } cv;
    cv.h2 = h;
    return cv.u;
}

// ---------------- embed + rel ----------------
__global__ void embed_kernel(const float* __restrict__ vm_states,
                             const float* __restrict__ num_step,
                             const float* __restrict__ pm_states,
                             const float* __restrict__ W_pm, const float* __restrict__ b_pm,
                             const float* __restrict__ W_vm, const float* __restrict__ b_vm,
                             const float* __restrict__ critic) {
    int b = blockIdx.y;
    int l = blockIdx.x;
    int d = threadIdx.x;
    float val;
    if (l == 0) {
        val = num_step[b];
    } else if (l <= NUM_PM) {
        const float* pm = pm_states + (b * NUM_PM + (l - 1)) * PM_COV;
        float acc = b_pm[d];
        #pragma unroll
        for (int c = 0; c < PM_COV; c++) acc += pm[c] * W_pm[c * DMODEL + d];
        val = acc;
    } else if (l <= NUM_PM + NUM_VM) {
        const float* vm = vm_states + (b * NUM_VM + (l - 1 - NUM_PM)) * 7;
        float acc = b_vm[d];
        #pragma unroll
        for (int c = 0; c < 6; c++) acc += vm[c] * W_vm[c * DMODEL + d];
        val = acc;
    } else {
        val = critic[d];
    }
    g_x[(b * SEQL + l) * DMODEL + d] = val;
    if (d == 0) {
        int r = -100;
        if (l >= 1 && l <= NUM_PM) r = l - 1;
        else if (l > NUM_PM && l < SEQL - 1)
            r = (int)vm_states[(b * NUM_VM + (l - 1 - NUM_PM)) * 7 + 6];
        g_rel[b * SEQL + l] = r;
    }
}

// ---------------- group list build ----------------
__global__ void build_init() {
    int i = blockIdx.x * 256 + threadIdx.x;
    if (i >= BATCH * NUM_PM) return;
    int r = i % NUM_PM;
    g_cnt[i] = 1;
    g_list[i * CAP] = 1 + r;
}

__global__ void build_vm(const float* __restrict__ vm_states) {
    int i = blockIdx.x * 256 + threadIdx.x;
    if (i >= BATCH * NUM_VM) return;
    int b = i / NUM_VM, j = i % NUM_VM;
    int r = (int)vm_states[(b * NUM_VM + j) * 7 + 6];
    int p = atomicAdd(&g_cnt[b * NUM_PM + r], 1);
    if (p < CAP) g_list[(b * NUM_PM + r) * CAP + p] = NUM_PM + 1 + j;
}

// ---------------- weight transpose + fp16: src [K][N] -> dst [N][K] ----------------
__global__ void transpose_half(const float* __restrict__ src, __half* __restrict__ dst,
                               int K, int N) {
    __shared__ float t[32][33];
    int l = blockIdx.z;
    const float* s = src + l * K * N;
    __half* d = dst + l * K * N;
    int k0 = blockIdx.x * 32, n0 = blockIdx.y * 32;
    int tx = threadIdx.x, ty = threadIdx.y;
    #pragma unroll
    for (int j = 0; j < 32; j += 8)
        t[ty + j][tx] = s[(k0 + ty + j) * N + n0 + tx];
    __syncthreads();
    #pragma unroll
    for (int j = 0; j < 32; j += 8)
        d[(n0 + ty + j) * K + k0 + tx] = __float2half(t[tx][ty + j]);
}

// ---------------- layernorm: warp per row, fp16 output ----------------
__global__ void ln_kernel(const float* __restrict__ gamma, const float* __restrict__ beta) {
    int row = blockIdx.x * 8 + (threadIdx.x >> 5);
    if (row >= MROWS) return;
    int lane = threadIdx.x & 31;
    const float4* xr = (const float4*)(g_x + row * DMODEL) + lane * 2;
    float4 a = xr[0], c4 = xr[1];
    float v8[8] = {a.x, a.y, a.z, a.w, c4.x, c4.y, c4.z, c4.w};
    float s = 0.f;
    #pragma unroll
    for (int t = 0; t < 8; t++) s += v8[t];
    #pragma unroll
    for (int o = 16; o > 0; o >>= 1) s += __shfl_xor_sync(0xffffffffu, s, o);
    float mean = s * (1.0f / DMODEL);
    float vs = 0.f;
    #pragma unroll
    for (int t = 0; t < 8; t++) { v8[t] -= mean; vs += v8[t] * v8[t]; }
    #pragma unroll
    for (int o = 16; o > 0; o >>= 1) vs += __shfl_xor_sync(0xffffffffu, vs, o);
    float r = rsqrtf(vs * (1.0f / DMODEL) + 1e-5f);
    const float4* gg = (const float4*)gamma + lane * 2;
    const float4* bb = (const float4*)beta + lane * 2;
    float4 g0 = gg[0], g1 = gg[1], b0 = bb[0], b1 = bb[1];
    float ge[8] = {g0.x, g0.y, g0.z, g0.w, g1.x, g1.y, g1.z, g1.w};
    float be[8] = {b0.x, b0.y, b0.z, b0.w, b1.x, b1.y, b1.z, b1.w};
    uint4 pack;
    pack.x = h2_u32(__floats2half2_rn(v8[0] * r * ge[0] + be[0], v8[1] * r * ge[1] + be[1]));
    pack.y = h2_u32(__floats2half2_rn(v8[2] * r * ge[2] + be[2], v8[3] * r * ge[3] + be[3]));
    pack.z = h2_u32(__floats2half2_rn(v8[4] * r * ge[4] + be[4], v8[5] * r * ge[5] + be[5]));
    pack.w = h2_u32(__floats2half2_rn(v8[6] * r * ge[6] + be[6], v8[7] * r * ge[7] + be[7]));
    *((uint4*)(g_h + row * DMODEL) + lane) = pack;
}

// ---------------- GELU (tanh approx) ----------------
__device__ __forceinline__ float gelu_f(float x) {
    float x3 = x * x * x;
    float t = tanhf(0.7978845608028654f * (x + 0.044715f * x3));
    return 0.5f * x * (1.0f + t);
}

// ================= fp16 mma.sync GEMM =================
// Block 128x128, 8 warps (2x4), warp tile 64x32, BK=64 halfs, double-buffered cp.async.
// Smem half strides: 72 halfs/row (144 B) -> conflict-free fragment LDS.
#define BKh 64
#define HSTRIDE 72
#define A_STAGE_H (128 * HSTRIDE)              // 9216 halfs
#define STAGE_H   (2 * A_STAGE_H)              // A + B
#define GEMM_SMEM_H (2 * STAGE_H * 2)          // bytes: 73728

__device__ __forceinline__ void cp16s(uint32_t saddr, const void* g) {
    asm volatile("cp.async.cg.shared.global [%0], [%1], 16;\n" :: "r"(saddr), "l"(g));
}
#define CP_COMMIT() asm volatile("cp.async.commit_group;\n" ::: "memory")
#define CP_WAIT(n)  asm volatile("cp.async.wait_group %0;\n" :: "n"(n) : "memory")
__device__ __forceinline__ uint32_t smem_u32(const void* p) {
    uint32_t a;
    asm("{ .reg .u64 t; cvta.to.shared.u64 t, %1; cvt.u32.u64 %0, t; }" : "=r"(a) : "l"(p));
    return a;
}

// z-dim selects among up to 3 weight/bias/output sets (QKV fusion).
__global__ void __launch_bounds__(256, 2)
gemm_h(const __half* __restrict__ A,
       const __half* __restrict__ Wt0, const __half* __restrict__ Wt1,
       const __half* __restrict__ Wt2,
       const float* __restrict__ bias0, const float* __restrict__ bias1,
       const float* __restrict__ bias2,
       void* __restrict__ C0, void* __restrict__ C1, void* __restrict__ C2,
       const float* __restrict__ res,
       int M, int N, int K, int act) {
    const __half* Wt  = (blockIdx.z == 0) ? Wt0   : (blockIdx.z == 1) ? Wt1   : Wt2;
    const float* bias = (blockIdx.z == 0) ? bias0 : (blockIdx.z == 1) ? bias1 : bias2;
    void* Cv          = (blockIdx.z == 0) ? C0    : (blockIdx.z == 1) ? C1    : C2;

    extern __shared__ __half smh[];
    const int tid = threadIdx.x;
    const int m0 = blockIdx.y * 128;
    const int n0 = blockIdx.x * 128;
    const int lane = tid & 31;
    const int warp = tid >> 5;
    const int wm = warp >> 2;          // 0..1
    const int wn = warp & 3;           // 0..3
    const int lq = lane >> 2;          // 0..7
    const int lr = lane & 3;           // 0..3

    float c[4][4][4];
    #pragma unroll
    for (int i = 0; i < 4; i++)
        #pragma unroll
        for (int j = 0; j < 4; j++)
            #pragma unroll
            for (int p = 0; p < 4; p++) c[i][j][p] = 0.f;

    uint32_t sb = smem_u32(smh);

    auto loadStage = [&](int stage, int ct) {
        int kc = ct * BKh;
        uint32_t offA = sb + stage * (STAGE_H * 2);
        uint32_t offB = offA + A_STAGE_H * 2;
        #pragma unroll
        for (int p = 0; p < 4; p++) {
            int i = tid + p * 256;
            int r = i >> 3, seg = i & 7;             // 8 segs of 8 halfs = 64 halfs
            int gm = m0 + r;
            if (gm >= M) gm = M - 1;
            cp16s(offA + (r * HSTRIDE + seg * 8) * 2, A + gm * K + kc + seg * 8);
            cp16s(offB + (r * HSTRIDE + seg * 8) * 2, Wt + (n0 + r) * K + kc + seg * 8);
        }
    };

    auto computeStage = [&](int stage) {
        const __half* As = smh + stage * STAGE_H;
        const __half* Bs = As + A_STAGE_H;
        #pragma unroll
        for (int kk = 0; kk < BKh; kk += 16) {
            uint32_t af[4][4], bf[4][2];
            #pragma unroll
            for (int tm = 0; tm < 4; tm++) {
                const __half* ap = As + (wm * 64 + tm * 16 + lq) * HSTRIDE + kk + 2 * lr;
                af[tm][0] = *(const uint32_t*)(ap);
                af[tm][1] = *(const uint32_t*)(ap + 8 * HSTRIDE);
                af[tm][2] = *(const uint32_t*)(ap + 8);
                af[tm][3] = *(const uint32_t*)(ap + 8 * HSTRIDE + 8);
            }
            #pragma unroll
            for (int tn = 0; tn < 4; tn++) {
                const __half* bp = Bs + (wn * 32 + tn * 8 + lq) * HSTRIDE + kk + 2 * lr;
                bf[tn][0] = *(const uint32_t*)(bp);
                bf[tn][1] = *(const uint32_t*)(bp + 8);
            }
            #pragma unroll
            for (int tm = 0; tm < 4; tm++)
                #pragma unroll
                for (int tn = 0; tn < 4; tn++) {
                    asm volatile(
                        "mma.sync.aligned.m16n8k16.row.col.f32.f16.f16.f32 "
                        "{%0,%1,%2,%3}, {%4,%5,%6,%7}, {%8,%9}, {%0,%1,%2,%3};\n"
                        : "+f"(c[tm][tn][0]), "+f"(c[tm][tn][1]),
                          "+f"(c[tm][tn][2]), "+f"(c[tm][tn][3])
                        : "r"(af[tm][0]), "r"(af[tm][1]), "r"(af[tm][2]), "r"(af[tm][3]),
                          "r"(bf[tn][0]), "r"(bf[tn][1]));
                }
        }
    };

    const int KT = K / BKh;
    loadStage(0, 0);
    CP_COMMIT();
    int buf = 0;
    for (int ct = 0; ct < KT; ct++) {
        if (ct + 1 < KT) {
            loadStage(buf ^ 1, ct + 1);
            CP_COMMIT();
            CP_WAIT(1);
        } else {
            CP_WAIT(0);
        }
        __syncthreads();
        computeStage(buf);
        __syncthreads();
        buf ^= 1;
    }

    // epilogue
    #pragma unroll
    for (int tm = 0; tm < 4; tm++) {
        #pragma unroll
        for (int tn = 0; tn < 4; tn++) {
            int row0 = m0 + wm * 64 + tm * 16 + lq;
            int col = n0 + wn * 32 + tn * 8 + 2 * lr;
            #pragma unroll
            for (int half_i = 0; half_i < 2; half_i++) {
                int r = row0 + half_i * 8;
                if (r < M) {
                    float v0 = c[tm][tn][half_i * 2 + 0] + bias[col];
                    float v1 = c[tm][tn][half_i * 2 + 1] + bias[col + 1];
                    if (res) { v0 += res[r * N + col]; v1 += res[r * N + col + 1]; }
                    if (act) {
                        __half2 hv = __floats2half2_rn(gelu_f(v0), gelu_f(v1));
                        *(__half2*)((__half*)Cv + r * N + col) = hv;
                    } else {
                        float* C = (float*)Cv;
                        C[r * N + col] = v0;
                        C[r * N + col + 1] = v1;
                    }
                }
            }
        }
    }
}

// ---------------- sparse attention: warp per (b, query), fp16 output ----------------
__global__ void attn_kernel() {
    int gw = blockIdx.x * 8 + (threadIdx.x >> 5);
    if (gw >= BATCH * SEQL) return;
    int b = gw / SEQL;
    int l = gw - b * SEQL;
    int lane = threadIdx.x & 31;
    int row = b * SEQL + l;

    if (l == 0 || l == SEQL - 1) {
        #pragma unroll
        for (int t = 0; t < 8; t++)
            g_o[row * DMODEL + lane + 32 * t] = __float2half(g_v[row * DMODEL + lane + 32 * t]);
        return;
    }

    int r = g_rel[row];
    int cnt = g_cnt[b * NUM_PM + r];
    if (cnt > CAP) cnt = CAP;
    const int* lst = g_list + (b * NUM_PM + r) * CAP;

    const float scale = 0.17677669529663687f;
    float q8[8], o8[8], mx[8], sum[8];
    #pragma unroll
    for (int h = 0; h < 8; h++) {
        q8[h] = g_q[row * DMODEL + lane + 32 * h] * scale;
        o8[h] = 0.f; mx[h] = -1e30f; sum[h] = 0.f;
    }

    for (int i = 0; i < cnt; i++) {
        int krow = b * SEQL + lst[i];
        float k8[8], v8[8];
        #pragma unroll
        for (int t = 0; t < 8; t++) {
            k8[t] = g_k[krow * DMODEL + lane + 32 * t];
            v8[t] = g_v[krow * DMODEL + lane + 32 * t];
        }
        #pragma unroll
        for (int h = 0; h < 8; h++) {
            float d = q8[h] * k8[h];
            #pragma unroll
            for (int o = 16; o > 0; o >>= 1) d += __shfl_xor_sync(0xffffffffu, d, o);
            float nm = fmaxf(mx[h], d);
            float corr = __expf(mx[h] - nm);
            float p = __expf(d - nm);
            sum[h] = sum[h] * corr + p;
            o8[h] = o8[h] * corr + p * v8[h];
            mx[h] = nm;
        }
    }
    #pragma unroll
    for (int h = 0; h < 8; h++)
        g_o[row * DMODEL + lane + 32 * h] = __float2half(o8[h] / sum[h]);
}

// ---------------- output head ----------------
__global__ void out_kernel(const float* __restrict__ W_out, const float* __restrict__ b_out,
                           float* __restrict__ out) {
    int b = blockIdx.y;
    int warp = threadIdx.x >> 5;
    int lane = threadIdx.x & 31;
    int j = blockIdx.x * 8 + warp;
    if (j >= NUM_VM) return;
    int row = b * SEQL + NUM_PM + 1 + j;
    float acc = 0.f;
    #pragma unroll
    for (int d = lane; d < DMODEL; d += 32)
        acc += g_x[row * DMODEL + d] * W_out[d];
    #pragma unroll
    for (int o = 16; o > 0; o >>= 1) acc += __shfl_xor_sync(0xffffffffu, acc, o);
    if (lane == 0) out[b * NUM_VM + j] = acc + b_out[0];
}

// ---------------- host launcher ----------------
extern "C" void kernel_launch(void* const* d_in, const int* in_sizes, int n_in,
                              void* d_out, int out_size) {
    const float* vm_states = (const float*)d_in[0];
    const float* num_step  = (const float*)d_in[1];
    const float* pm_states = (const float*)d_in[2];
    const float* W_pm = (const float*)d_in[3];
    const float* b_pm = (const float*)d_in[4];
    const float* W_vm = (const float*)d_in[5];
    const float* b_vm = (const float*)d_in[6];
    const float* critic = (const float*)d_in[7];
    const float* ln1_g = (const float*)d_in[8];
    const float* ln1_b = (const float*)d_in[9];
    const float* Wq = (const float*)d_in[10];
    const float* bq = (const float*)d_in[11];
    const float* Wk = (const float*)d_in[12];
    const float* bk = (const float*)d_in[13];
    const float* Wv = (const float*)d_in[14];
    const float* bv = (const float*)d_in[15];
    const float* Wo = (const float*)d_in[16];
    const float* bo = (const float*)d_in[17];
    const float* ln2_g = (const float*)d_in[18];
    const float* ln2_b = (const float*)d_in[19];
    const float* W1 = (const float*)d_in[20];
    const float* b1 = (const float*)d_in[21];
    const float* W2 = (const float*)d_in[22];
    const float* b2 = (const float*)d_in[23];
    const float* W_out = (const float*)d_in[24];
    const float* b_out = (const float*)d_in[25];
    float* out = (float*)d_out;

    void *ph, *pq, *pk, *pv, *po, *pf, *px;
    void *pWq, *pWk, *pWv, *pWo, *pW1, *pW2;
    cudaGetSymbolAddress(&px, g_x);
    cudaGetSymbolAddress(&ph, g_h);
    cudaGetSymbolAddress(&pq, g_q);
    cudaGetSymbolAddress(&pk, g_k);
    cudaGetSymbolAddress(&pv, g_v);
    cudaGetSymbolAddress(&po, g_o);
    cudaGetSymbolAddress(&pf, g_ffn);
    cudaGetSymbolAddress(&pWq, g_Wqt);
    cudaGetSymbolAddress(&pWk, g_Wkt);
    cudaGetSymbolAddress(&pWv, g_Wvt);
    cudaGetSymbolAddress(&pWo, g_Wot);
    cudaGetSymbolAddress(&pW1, g_W1t);
    cudaGetSymbolAddress(&pW2, g_W2t);
    float* x = (float*)px;
    __half* h = (__half*)ph;
    float* q = (float*)pq;
    float* k = (float*)pk;
    float* v = (float*)pv;
    __half* o = (__half*)po;
    __half* f = (__half*)pf;
    __half* rWq = (__half*)pWq;
    __half* rWk = (__half*)pWk;
    __half* rWv = (__half*)pWv;
    __half* rWo = (__half*)pWo;
    __half* rW1 = (__half*)pW1;
    __half* rW2 = (__half*)pW2;

    cudaFuncSetAttribute(gemm_h, cudaFuncAttributeMaxDynamicSharedMemorySize, GEMM_SMEM_H);

    // transpose + fp16 weights: [K][N] -> [N][K]
    dim3 tb(32, 8);
    transpose_half<<<dim3(8, 8, NLAYER), tb>>>(Wq, rWq, DMODEL, DMODEL);
    transpose_half<<<dim3(8, 8, NLAYER), tb>>>(Wk, rWk, DMODEL, DMODEL);
    transpose_half<<<dim3(8, 8, NLAYER), tb>>>(Wv, rWv, DMODEL, DMODEL);
    transpose_half<<<dim3(8, 8, NLAYER), tb>>>(Wo, rWo, DMODEL, DMODEL);
    transpose_half<<<dim3(8, 32, NLAYER), tb>>>(W1, rW1, DMODEL, DFF);
    transpose_half<<<dim3(32, 8, NLAYER), tb>>>(W2, rW2, DFF, DMODEL);

    embed_kernel<<<dim3(SEQL, BATCH), DMODEL>>>(vm_states, num_step, pm_states,
                                                W_pm, b_pm, W_vm, b_vm, critic);
    build_init<<<(BATCH * NUM_PM + 255) / 256, 256>>>();
    build_vm<<<(BATCH * NUM_VM + 255) / 256, 256>>>(vm_states);

    const int M = MROWS;
    const int gridM = (M + 127) / 128;              // 82
    dim3 gQKV(DMODEL / 128, gridM, 3);              // (2, 82, 3)
    dim3 g256(DMODEL / 128, gridM, 1);              // (2, 82)
    dim3 g1024(DFF / 128, gridM, 1);                // (8, 82)
    dim3 gln((MROWS + 7) / 8);
    dim3 gattn((BATCH * SEQL + 7) / 8);

    for (int l = 0; l < NLAYER; l++) {
        ln_kernel<<<gln, 256>>>(ln1_g + l * DMODEL, ln1_b + l * DMODEL);
        gemm_h<<<gQKV, 256, GEMM_SMEM_H>>>(h,
            rWq + l * DMODEL * DMODEL, rWk + l * DMODEL * DMODEL, rWv + l * DMODEL * DMODEL,
            bq + l * DMODEL, bk + l * DMODEL, bv + l * DMODEL,
            q, k, v, nullptr, M, DMODEL, DMODEL, 0);
        attn_kernel<<<gattn, 256>>>();
        gemm_h<<<g256, 256, GEMM_SMEM_H>>>(o,
            rWo + l * DMODEL * DMODEL, rWo + l * DMODEL * DMODEL, rWo + l * DMODEL * DMODEL,
            bo + l * DMODEL, bo + l * DMODEL, bo + l * DMODEL,
            x, x, x, x, M, DMODEL, DMODEL, 0);
        ln_kernel<<<gln, 256>>>(ln2_g + l * DMODEL, ln2_b + l * DMODEL);
        gemm_h<<<g1024, 256, GEMM_SMEM_H>>>(h,
            rW1 + l * DMODEL * DFF, rW1 + l * DMODEL * DFF, rW1 + l * DMODEL * DFF,
            b1 + l * DFF, b1 + l * DFF, b1 + l * DFF,
            f, f, f, nullptr, M, DFF, DMODEL, 1);
        gemm_h<<<g256, 256, GEMM_SMEM_H>>>(f,
            rW2 + l * DFF * DMODEL, rW2 + l * DFF * DMODEL, rW2 + l * DFF * DMODEL,
            b2 + l * DMODEL, b2 + l * DMODEL, b2 + l * DMODEL,
            x, x, x, x, M, DMODEL, DFF, 0);
    }

    out_kernel<<<dim3((NUM_VM + 7) / 8, BATCH), 256>>>(W_out, b_out, out);
}

// round 10
// speedup vs baseline: 6.5597x; 1.0199x over previous
#include <cuda_runtime.h>
#include <cuda_fp16.h>
#include <cstdint>

#define BATCH 8
#define NUM_PM 300
#define NUM_VM 1000
#define PM_COV 8
#define DMODEL 256
#define NHEAD 8
#define DHEAD 32
#define DFF 1024
#define NLAYER 3
#define SEQL (NUM_PM + NUM_VM + 2)   // 1302
#define MROWS (BATCH * SEQL)          // 10416
#define CAP 64

// ---------------- static scratch ----------------
__device__ float  g_x[MROWS * DMODEL];
__device__ __half g_h[MROWS * DMODEL];
__device__ float  g_q[MROWS * DMODEL];
__device__ float  g_k[MROWS * DMODEL];
__device__ float  g_v[MROWS * DMODEL];
__device__ __half g_o[MROWS * DMODEL];
__device__ __half g_ffn[MROWS * DFF];
__device__ int    g_rel[MROWS];
__device__ int    g_cnt[BATCH * NUM_PM];
__device__ int    g_list[BATCH * NUM_PM * CAP];
// transposed + fp16 weights, [N][K] K-major
__device__ __half g_Wqt[NLAYER * DMODEL * DMODEL];
__device__ __half g_Wkt[NLAYER * DMODEL * DMODEL];
__device__ __half g_Wvt[NLAYER * DMODEL * DMODEL];
__device__ __half g_Wot[NLAYER * DMODEL * DMODEL];
__device__ __half g_W1t[NLAYER * DMODEL * DFF];
__device__ __half g_W2t[NLAYER * DFF * DMODEL];

__device__ __forceinline__ uint32_t h2_u32(__half2 h) {
    union { __half2 h2; uint32_t u; } cv;
    cv.h2 = h;
    return cv.u;
}

// ---------------- embed + rel ----------------
__global__ void embed_kernel(const float* __restrict__ vm_states,
                             const float* __restrict__ num_step,
                             const float* __restrict__ pm_states,
                             const float* __restrict__ W_pm, const float* __restrict__ b_pm,
                             const float* __restrict__ W_vm, const float* __restrict__ b_vm,
                             const float* __restrict__ critic) {
    int b = blockIdx.y;
    int l = blockIdx.x;
    int d = threadIdx.x;
    float val;
    if (l == 0) {
        val = num_step[b];
    } else if (l <= NUM_PM) {
        const float* pm = pm_states + (b * NUM_PM + (l - 1)) * PM_COV;
        float acc = b_pm[d];
        #pragma unroll
        for (int c = 0; c < PM_COV; c++) acc += pm[c] * W_pm[c * DMODEL + d];
        val = acc;
    } else if (l <= NUM_PM + NUM_VM) {
        const float* vm = vm_states + (b * NUM_VM + (l - 1 - NUM_PM)) * 7;
        float acc = b_vm[d];
        #pragma unroll
        for (int c = 0; c < 6; c++) acc += vm[c] * W_vm[c * DMODEL + d];
        val = acc;
    } else {
        val = critic[d];
    }
    g_x[(b * SEQL + l) * DMODEL + d] = val;
    if (d == 0) {
        int r = -100;
        if (l >= 1 && l <= NUM_PM) r = l - 1;
        else if (l > NUM_PM && l < SEQL - 1)
            r = (int)vm_states[(b * NUM_VM + (l - 1 - NUM_PM)) * 7 + 6];
        g_rel[b * SEQL + l] = r;
    }
}

// ---------------- group list build ----------------
__global__ void build_init() {
    int i = blockIdx.x * 256 + threadIdx.x;
    if (i >= BATCH * NUM_PM) return;
    int r = i % NUM_PM;
    g_cnt[i] = 1;
    g_list[i * CAP] = 1 + r;
}

__global__ void build_vm(const float* __restrict__ vm_states) {
    int i = blockIdx.x * 256 + threadIdx.x;
    if (i >= BATCH * NUM_VM) return;
    int b = i / NUM_VM, j = i % NUM_VM;
    int r = (int)vm_states[(b * NUM_VM + j) * 7 + 6];
    int p = atomicAdd(&g_cnt[b * NUM_PM + r], 1);
    if (p < CAP) g_list[(b * NUM_PM + r) * CAP + p] = NUM_PM + 1 + j;
}

// ---------------- fused weight transpose + fp16: all 6 weights, one launch ----------------
__global__ void transpose_all(const float* __restrict__ Wq, const float* __restrict__ Wk,
                              const float* __restrict__ Wv, const float* __restrict__ Wo,
                              const float* __restrict__ W1, const float* __restrict__ W2) {
    __shared__ float t[32][33];
    int bid = blockIdx.x;
    const float* src;
    __half* dst;
    int K, N, ti;
    if (bid < 768) {
        int w = bid / 192;
        ti = bid % 192;
        src = (w == 0) ? Wq : (w == 1) ? Wk : (w == 2) ? Wv : Wo;
        dst = (w == 0) ? g_Wqt : (w == 1) ? g_Wkt : (w == 2) ? g_Wvt : g_Wot;
        K = DMODEL; N = DMODEL;
    } else if (bid < 1536) {
        ti = bid - 768; src = W1; dst = g_W1t; K = DMODEL; N = DFF;
    } else {
        ti = bid - 1536; src = W2; dst = g_W2t; K = DFF; N = DMODEL;
    }
    int tilesN = N >> 5;
    int perLayer = (K >> 5) * tilesN;
    int layer = ti / perLayer;
    int tt = ti - layer * perLayer;
    int k0 = (tt / tilesN) << 5, n0 = (tt % tilesN) << 5;
    const float* s = src + layer * K * N;
    __half* d = dst + layer * K * N;
    int tx = threadIdx.x, ty = threadIdx.y;
    #pragma unroll
    for (int j = 0; j < 32; j += 8)
        t[ty + j][tx] = s[(k0 + ty + j) * N + n0 + tx];
    __syncthreads();
    #pragma unroll
    for (int j = 0; j < 32; j += 8)
        d[(n0 + ty + j) * K + k0 + tx] = __float2half(t[tx][ty + j]);
}

// ---------------- layernorm: warp per row, fp16 output ----------------
__global__ void ln_kernel(const float* __restrict__ gamma, const float* __restrict__ beta) {
    int row = blockIdx.x * 8 + (threadIdx.x >> 5);
    if (row >= MROWS) return;
    int lane = threadIdx.x & 31;
    const float4* xr = (const float4*)(g_x + row * DMODEL) + lane * 2;
    float4 a = xr[0], c4 = xr[1];
    float v8[8] = {a.x, a.y, a.z, a.w, c4.x, c4.y, c4.z, c4.w};
    float s = 0.f;
    #pragma unroll
    for (int t = 0; t < 8; t++) s += v8[t];
    #pragma unroll
    for (int o = 16; o > 0; o >>= 1) s += __shfl_xor_sync(0xffffffffu, s, o);
    float mean = s * (1.0f / DMODEL);
    float vs = 0.f;
    #pragma unroll
    for (int t = 0; t < 8; t++) { v8[t] -= mean; vs += v8[t] * v8[t]; }
    #pragma unroll
    for (int o = 16; o > 0; o >>= 1) vs += __shfl_xor_sync(0xffffffffu, vs, o);
    float r = rsqrtf(vs * (1.0f / DMODEL) + 1e-5f);
    const float4* gg = (const float4*)gamma + lane * 2;
    const float4* bb = (const float4*)beta + lane * 2;
    float4 g0 = gg[0], g1 = gg[1], b0 = bb[0], b1 = bb[1];
    float ge[8] = {g0.x, g0.y, g0.z, g0.w, g1.x, g1.y, g1.z, g1.w};
    float be[8] = {b0.x, b0.y, b0.z, b0.w, b1.x, b1.y, b1.z, b1.w};
    uint4 pack;
    pack.x = h2_u32(__floats2half2_rn(v8[0] * r * ge[0] + be[0], v8[1] * r * ge[1] + be[1]));
    pack.y = h2_u32(__floats2half2_rn(v8[2] * r * ge[2] + be[2], v8[3] * r * ge[3] + be[3]));
    pack.z = h2_u32(__floats2half2_rn(v8[4] * r * ge[4] + be[4], v8[5] * r * ge[5] + be[5]));
    pack.w = h2_u32(__floats2half2_rn(v8[6] * r * ge[6] + be[6], v8[7] * r * ge[7] + be[7]));
    *((uint4*)(g_h + row * DMODEL) + lane) = pack;
}

// ---------------- GELU (tanh approx) ----------------
__device__ __forceinline__ float gelu_f(float x) {
    float x3 = x * x * x;
    float t = tanhf(0.7978845608028654f * (x + 0.044715f * x3));
    return 0.5f * x * (1.0f + t);
}

// ================= fp16 mma.sync GEMM, 3-stage / single-barrier pipeline =================
// Block 128x128, 8 warps (2x4), warp tile 64x32, BK=64 halfs.
#define BKh 64
#define HSTRIDE 72
#define A_STAGE_H (128 * HSTRIDE)              // 9216 halfs
#define STAGE_H   (2 * A_STAGE_H)              // A + B = 18432 halfs
#define NSTAGE 3
#define GEMM_SMEM_H (NSTAGE * STAGE_H * 2)     // 110592 bytes

__device__ __forceinline__ void cp16s(uint32_t saddr, const void* g) {
    asm volatile("cp.async.cg.shared.global [%0], [%1], 16;\n" :: "r"(saddr), "l"(g));
}
#define CP_COMMIT() asm volatile("cp.async.commit_group;\n" ::: "memory")
#define CP_WAIT(n)  asm volatile("cp.async.wait_group %0;\n" :: "n"(n) : "memory")
__device__ __forceinline__ uint32_t smem_u32(const void* p) {
    uint32_t a;
    asm("{ .reg .u64 t; cvta.to.shared.u64 t, %1; cvt.u32.u64 %0, t; }" : "=r"(a) : "l"(p));
    return a;
}

// z-dim selects among up to 3 weight/bias/output sets (QKV fusion).
__global__ void __launch_bounds__(256, 2)
gemm_h(const __half* __restrict__ A,
       const __half* __restrict__ Wt0, const __half* __restrict__ Wt1,
       const __half* __restrict__ Wt2,
       const float* __restrict__ bias0, const float* __restrict__ bias1,
       const float* __restrict__ bias2,
       void* __restrict__ C0, void* __restrict__ C1, void* __restrict__ C2,
       const float* __restrict__ res,
       int M, int N, int K, int act) {
    const __half* Wt  = (blockIdx.z == 0) ? Wt0   : (blockIdx.z == 1) ? Wt1   : Wt2;
    const float* bias = (blockIdx.z == 0) ? bias0 : (blockIdx.z == 1) ? bias1 : bias2;
    void* Cv          = (blockIdx.z == 0) ? C0    : (blockIdx.z == 1) ? C1    : C2;

    extern __shared__ __half smh[];
    const int tid = threadIdx.x;
    const int m0 = blockIdx.y * 128;
    const int n0 = blockIdx.x * 128;
    const int lane = tid & 31;
    const int warp = tid >> 5;
    const int wm = warp >> 2;          // 0..1
    const int wn = warp & 3;           // 0..3
    const int lq = lane >> 2;          // 0..7
    const int lr = lane & 3;           // 0..3

    float c[4][4][4];
    #pragma unroll
    for (int i = 0; i < 4; i++)
        #pragma unroll
        for (int j = 0; j < 4; j++)
            #pragma unroll
            for (int p = 0; p < 4; p++) c[i][j][p] = 0.f;

    uint32_t sb = smem_u32(smh);

    auto loadStage = [&](int stage, int ct) {
        int kc = ct * BKh;
        uint32_t offA = sb + stage * (STAGE_H * 2);
        uint32_t offB = offA + A_STAGE_H * 2;
        #pragma unroll
        for (int p = 0; p < 4; p++) {
            int i = tid + p * 256;
            int r = i >> 3, seg = i & 7;             // 8 segs of 8 halfs = 64 halfs
            int gm = m0 + r;
            if (gm >= M) gm = M - 1;
            cp16s(offA + (r * HSTRIDE + seg * 8) * 2, A + gm * K + kc + seg * 8);
            cp16s(offB + (r * HSTRIDE + seg * 8) * 2, Wt + (n0 + r) * K + kc + seg * 8);
        }
    };

    auto computeStage = [&](int stage) {
        const __half* As = smh + stage * STAGE_H;
        const __half* Bs = As + A_STAGE_H;
        #pragma unroll
        for (int kk = 0; kk < BKh; kk += 16) {
            uint32_t af[4][4], bf[4][2];
            #pragma unroll
            for (int tm = 0; tm < 4; tm++) {
                const __half* ap = As + (wm * 64 + tm * 16 + lq) * HSTRIDE + kk + 2 * lr;
                af[tm][0] = *(const uint32_t*)(ap);
                af[tm][1] = *(const uint32_t*)(ap + 8 * HSTRIDE);
                af[tm][2] = *(const uint32_t*)(ap + 8);
                af[tm][3] = *(const uint32_t*)(ap + 8 * HSTRIDE + 8);
            }
            #pragma unroll
            for (int tn = 0; tn < 4; tn++) {
                const __half* bp = Bs + (wn * 32 + tn * 8 + lq) * HSTRIDE + kk + 2 * lr;
                bf[tn][0] = *(const uint32_t*)(bp);
                bf[tn][1] = *(const uint32_t*)(bp + 8);
            }
            #pragma unroll
            for (int tm = 0; tm < 4; tm++)
                #pragma unroll
                for (int tn = 0; tn < 4; tn++) {
                    asm volatile(
                        "mma.sync.aligned.m16n8k16.row.col.f32.f16.f16.f32 "
                        "{%0,%1,%2,%3}, {%4,%5,%6,%7}, {%8,%9}, {%0,%1,%2,%3};\n"
                        : "+f"(c[tm][tn][0]), "+f"(c[tm][tn][1]),
                          "+f"(c[tm][tn][2]), "+f"(c[tm][tn][3])
                        : "r"(af[tm][0]), "r"(af[tm][1]), "r"(af[tm][2]), "r"(af[tm][3]),
                          "r"(bf[tn][0]), "r"(bf[tn][1]));
                }
        }
    };

    const int KT = K / BKh;
    // Correct single-barrier pipeline:
    //   at iter ct: prefetch chunk ct+1 into stage (ct+1)%3 (= stage computed at ct-2,
    //   guarded by the barrier inside iter ct-1), wait own groups (chunk ct done),
    //   then __syncthreads (cross-thread visibility of cp.async data), then compute.
    loadStage(0, 0);
    CP_COMMIT();
    for (int ct = 0; ct < KT; ct++) {
        if (ct + 1 < KT) {
            loadStage((ct + 1) % NSTAGE, ct + 1);
            CP_COMMIT();
            CP_WAIT(1);            // chunk ct complete (ct+1 may be in flight)
        } else {
            CP_WAIT(0);
        }
        __syncthreads();           // make all threads' cp.async data visible
        computeStage(ct % NSTAGE);
    }

    // epilogue
    #pragma unroll
    for (int tm = 0; tm < 4; tm++) {
        #pragma unroll
        for (int tn = 0; tn < 4; tn++) {
            int row0 = m0 + wm * 64 + tm * 16 + lq;
            int col = n0 + wn * 32 + tn * 8 + 2 * lr;
            #pragma unroll
            for (int half_i = 0; half_i < 2; half_i++) {
                int r = row0 + half_i * 8;
                if (r < M) {
                    float v0 = c[tm][tn][half_i * 2 + 0] + bias[col];
                    float v1 = c[tm][tn][half_i * 2 + 1] + bias[col + 1];
                    if (res) { v0 += res[r * N + col]; v1 += res[r * N + col + 1]; }
                    if (act) {
                        __half2 hv = __floats2half2_rn(gelu_f(v0), gelu_f(v1));
                        *(__half2*)((__half*)Cv + r * N + col) = hv;
                    } else {
                        float* C = (float*)Cv;
                        C[r * N + col] = v0;
                        C[r * N + col + 1] = v1;
                    }
                }
            }
        }
    }
}

// ---------------- sparse attention: warp per (b, query), fp16 output ----------------
__global__ void attn_kernel() {
    int gw = blockIdx.x * 8 + (threadIdx.x >> 5);
    if (gw >= BATCH * SEQL) return;
    int b = gw / SEQL;
    int l = gw - b * SEQL;
    int lane = threadIdx.x & 31;
    int row = b * SEQL + l;

    if (l == 0 || l == SEQL - 1) {
        #pragma unroll
        for (int t = 0; t < 8; t++)
            g_o[row * DMODEL + lane + 32 * t] = __float2half(g_v[row * DMODEL + lane + 32 * t]);
        return;
    }

    int r = g_rel[row];
    int cnt = g_cnt[b * NUM_PM + r];
    if (cnt > CAP) cnt = CAP;
    const int* lst = g_list + (b * NUM_PM + r) * CAP;

    const float scale = 0.17677669529663687f;
    float q8[8], o8[8], mx[8], sum[8];
    #pragma unroll
    for (int h = 0; h < 8; h++) {
        q8[h] = g_q[row * DMODEL + lane + 32 * h] * scale;
        o8[h] = 0.f; mx[h] = -1e30f; sum[h] = 0.f;
    }

    for (int i = 0; i < cnt; i++) {
        int krow = b * SEQL + lst[i];
        float k8[8], v8[8];
        #pragma unroll
        for (int t = 0; t < 8; t++) {
            k8[t] = g_k[krow * DMODEL + lane + 32 * t];
            v8[t] = g_v[krow * DMODEL + lane + 32 * t];
        }
        #pragma unroll
        for (int h = 0; h < 8; h++) {
            float d = q8[h] * k8[h];
            #pragma unroll
            for (int o = 16; o > 0; o >>= 1) d += __shfl_xor_sync(0xffffffffu, d, o);
            float nm = fmaxf(mx[h], d);
            float corr = __expf(mx[h] - nm);
            float p = __expf(d - nm);
            sum[h] = sum[h] * corr + p;
            o8[h] = o8[h] * corr + p * v8[h];
            mx[h] = nm;
        }
    }
    #pragma unroll
    for (int h = 0; h < 8; h++)
        g_o[row * DMODEL + lane + 32 * h] = __float2half(o8[h] / sum[h]);
}

// ---------------- output head ----------------
__global__ void out_kernel(const float* __restrict__ W_out, const float* __restrict__ b_out,
                           float* __restrict__ out) {
    int b = blockIdx.y;
    int warp = threadIdx.x >> 5;
    int lane = threadIdx.x & 31;
    int j = blockIdx.x * 8 + warp;
    if (j >= NUM_VM) return;
    int row = b * SEQL + NUM_PM + 1 + j;
    float acc = 0.f;
    #pragma unroll
    for (int d = lane; d < DMODEL; d += 32)
        acc += g_x[row * DMODEL + d] * W_out[d];
    #pragma unroll
    for (int o = 16; o > 0; o >>= 1) acc += __shfl_xor_sync(0xffffffffu, acc, o);
    if (lane == 0) out[b * NUM_VM + j] = acc + b_out[0];
}

// ---------------- host launcher ----------------
extern "C" void kernel_launch(void* const* d_in, const int* in_sizes, int n_in,
                              void* d_out, int out_size) {
    const float* vm_states = (const float*)d_in[0];
    const float* num_step  = (const float*)d_in[1];
    const float* pm_states = (const float*)d_in[2];
    const float* W_pm = (const float*)d_in[3];
    const float* b_pm = (const float*)d_in[4];
    const float* W_vm = (const float*)d_in[5];
    const float* b_vm = (const float*)d_in[6];
    const float* critic = (const float*)d_in[7];
    const float* ln1_g = (const float*)d_in[8];
    const float* ln1_b = (const float*)d_in[9];
    const float* Wq = (const float*)d_in[10];
    const float* bq = (const float*)d_in[11];
    const float* Wk = (const float*)d_in[12];
    const float* bk = (const float*)d_in[13];
    const float* Wv = (const float*)d_in[14];
    const float* bv = (const float*)d_in[15];
    const float* Wo = (const float*)d_in[16];
    const float* bo = (const float*)d_in[17];
    const float* ln2_g = (const float*)d_in[18];
    const float* ln2_b = (const float*)d_in[19];
    const float* W1 = (const float*)d_in[20];
    const float* b1 = (const float*)d_in[21];
    const float* W2 = (const float*)d_in[22];
    const float* b2 = (const float*)d_in[23];
    const float* W_out = (const float*)d_in[24];
    const float* b_out = (const float*)d_in[25];
    float* out = (float*)d_out;

    void *ph, *pq, *pk, *pv, *po, *pf, *px;
    void *pWq, *pWk, *pWv, *pWo, *pW1, *pW2;
    cudaGetSymbolAddress(&px, g_x);
    cudaGetSymbolAddress(&ph, g_h);
    cudaGetSymbolAddress(&pq, g_q);
    cudaGetSymbolAddress(&pk, g_k);
    cudaGetSymbolAddress(&pv, g_v);
    cudaGetSymbolAddress(&po, g_o);
    cudaGetSymbolAddress(&pf, g_ffn);
    cudaGetSymbolAddress(&pWq, g_Wqt);
    cudaGetSymbolAddress(&pWk, g_Wkt);
    cudaGetSymbolAddress(&pWv, g_Wvt);
    cudaGetSymbolAddress(&pWo, g_Wot);
    cudaGetSymbolAddress(&pW1, g_W1t);
    cudaGetSymbolAddress(&pW2, g_W2t);
    float* x = (float*)px;
    __half* h = (__half*)ph;
    float* q = (float*)pq;
    float* k = (float*)pk;
    float* v = (float*)pv;
    __half* o = (__half*)po;
    __half* f = (__half*)pf;
    __half* rWq = (__half*)pWq;
    __half* rWk = (__half*)pWk;
    __half* rWv = (__half*)pWv;
    __half* rWo = (__half*)pWo;
    __half* rW1 = (__half*)pW1;
    __half* rW2 = (__half*)pW2;

    cudaFuncSetAttribute(gemm_h, cudaFuncAttributeMaxDynamicSharedMemorySize, GEMM_SMEM_H);

    // all 6 weight transposes in one launch
    transpose_all<<<2304, dim3(32, 8)>>>(Wq, Wk, Wv, Wo, W1, W2);

    embed_kernel<<<dim3(SEQL, BATCH), DMODEL>>>(vm_states, num_step, pm_states,
                                                W_pm, b_pm, W_vm, b_vm, critic);
    build_init<<<(BATCH * NUM_PM + 255) / 256, 256>>>();
    build_vm<<<(BATCH * NUM_VM + 255) / 256, 256>>>(vm_states);

    const int M = MROWS;
    const int gridM = (M + 127) / 128;              // 82
    dim3 gQKV(DMODEL / 128, gridM, 3);              // (2, 82, 3)
    dim3 g256(DMODEL / 128, gridM, 1);              // (2, 82)
    dim3 g1024(DFF / 128, gridM, 1);                // (8, 82)
    dim3 gln((MROWS + 7) / 8);
    dim3 gattn((BATCH * SEQL + 7) / 8);

    for (int l = 0; l < NLAYER; l++) {
        ln_kernel<<<gln, 256>>>(ln1_g + l * DMODEL, ln1_b + l * DMODEL);
        gemm_h<<<gQKV, 256, GEMM_SMEM_H>>>(h,
            rWq + l * DMODEL * DMODEL, rWk + l * DMODEL * DMODEL, rWv + l * DMODEL * DMODEL,
            bq + l * DMODEL, bk + l * DMODEL, bv + l * DMODEL,
            q, k, v, nullptr, M, DMODEL, DMODEL, 0);
        attn_kernel<<<gattn, 256>>>();
        gemm_h<<<g256, 256, GEMM_SMEM_H>>>(o,
            rWo + l * DMODEL * DMODEL, rWo + l * DMODEL * DMODEL, rWo + l * DMODEL * DMODEL,
            bo + l * DMODEL, bo + l * DMODEL, bo + l * DMODEL,
            x, x, x, x, M, DMODEL, DMODEL, 0);
        ln_kernel<<<gln, 256>>>(ln2_g + l * DMODEL, ln2_b + l * DMODEL);
        gemm_h<<<g1024, 256, GEMM_SMEM_H>>>(h,
            rW1 + l * DMODEL * DFF, rW1 + l * DMODEL * DFF, rW1 + l * DMODEL * DFF,
            b1 + l * DFF, b1 + l * DFF, b1 + l * DFF,
            f, f, f, nullptr, M, DFF, DMODEL, 1);
        gemm_h<<<g256, 256, GEMM_SMEM_H>>>(f,
            rW2 + l * DFF * DMODEL, rW2 + l * DFF * DMODEL, rW2 + l * DFF * DMODEL,
            b2 + l * DMODEL, b2 + l * DMODEL, b2 + l * DMODEL,
            x, x, x, x, M, DMODEL, DFF, 0);
    }

    out_kernel<<<dim3((NUM_VM + 7) / 8, BATCH), 256>>>(W_out, b_out, out);
}